// round 1
// baseline (speedup 1.0000x reference)
#include <cuda_runtime.h>
#include <math.h>

// Problem constants
static constexpr int NT  = 4096;   // tokens
static constexpr int D   = 1024;   // model dim
static constexpr int HD  = 4096;   // hidden dim (4x)
static constexpr int NE  = 8;      // experts
static constexpr float CAPF = 4096.0f;  // capacity = int(1.0 * n)
static constexpr float GEPS = 1e-6f;

// Scratch (device globals: allocation-free rule)
__device__ int   g_expert[NT];
__device__ float g_score[NT];
__device__ int   g_cnt[NE];
__device__ int   g_list[NE][NT];
__device__ float g_colsum[NE];
__device__ float g_H[(size_t)NT * HD];   // 64 MB hidden activations, row = token id

__global__ void init_kernel() {
    int t = threadIdx.x;
    if (t < NE) { g_cnt[t] = 0; g_colsum[t] = 0.0f; }
}

// One warp per token: logits = x @ w_gate + b_gate, softmax, top-1.
__global__ void gate_kernel(const float* __restrict__ x,
                            const float* __restrict__ wg,
                            const float* __restrict__ bg) {
    int tok  = (blockIdx.x * blockDim.x + threadIdx.x) >> 5;
    int lane = threadIdx.x & 31;
    if (tok >= NT) return;
    const float* xr = x + (size_t)tok * D;
    float acc[NE];
#pragma unroll
    for (int e = 0; e < NE; e++) acc[e] = 0.0f;
    for (int i = lane; i < D; i += 32) {
        float xv = xr[i];
        const float* wr = wg + (size_t)i * NE;
#pragma unroll
        for (int e = 0; e < NE; e++) acc[e] = fmaf(xv, wr[e], acc[e]);
    }
#pragma unroll
    for (int off = 16; off; off >>= 1) {
#pragma unroll
        for (int e = 0; e < NE; e++)
            acc[e] += __shfl_xor_sync(0xffffffffu, acc[e], off);
    }
    if (lane == 0) {
        float l[NE];
        l[0] = acc[0] + bg[0];
        float m = l[0]; int a = 0;
#pragma unroll
        for (int e = 1; e < NE; e++) {
            l[e] = acc[e] + bg[e];
            if (l[e] > m) { m = l[e]; a = e; }  // ties -> lowest index (matches top_k)
        }
        float s = 0.0f;
#pragma unroll
        for (int e = 0; e < NE; e++) s += expf(l[e] - m);
        float p = 1.0f / s;  // softmax value at argmax (exp(0)/sum)
        g_expert[tok] = a;
        g_score[tok]  = p;
        int pos = atomicAdd(&g_cnt[a], 1);   // order-nondeterministic but value-irrelevant
        g_list[a][pos] = tok;
    }
}

// Deterministic per-expert colsum (fixed strided + tree order; bit-stable across replays)
__global__ void colsum_kernel() {
    __shared__ float red[256];
    int e = blockIdx.x;
    float s = 0.0f;
    for (int n = threadIdx.x; n < NT; n += 256)
        if (g_expert[n] == e) s += g_score[n];
    red[threadIdx.x] = s;
    __syncthreads();
    for (int o = 128; o; o >>= 1) {
        if (threadIdx.x < o) red[threadIdx.x] += red[threadIdx.x + o];
        __syncthreads();
    }
    if (threadIdx.x == 0) g_colsum[e] = red[0];
}

__global__ void loss_kernel(float* __restrict__ out, int loss_idx) {
    if (threadIdx.x == 0 && blockIdx.x == 0) {
        float load[NE];
        float tot = 0.0f;
#pragma unroll
        for (int e = 0; e < NE; e++) {
            float c = g_colsum[e];
            load[e] = c * CAPF / (c + GEPS);
            tot += load[e];
        }
        float imp = tot / (float)NT;
        float l = 0.0f;
#pragma unroll
        for (int e = 0; e < NE; e++) {
            float d = load[e] - imp;
            l += d * d;
        }
        out[loss_idx] = l / (float)NE;
    }
}

// Grouped-gather GEMM: C[tok, n] = act( A[tok, :K] @ B[e, :K, n] + bias[e, n] ) (* gate)
// Tile 128x128, BK=8, 256 threads, 8x8 per thread. Rows gathered via g_list[e].
template <int KDIM, int NDIM, bool GELU>
__global__ void __launch_bounds__(256, 2)
ffn_gemm(const float* __restrict__ A,
         const float* __restrict__ B,     // [NE, KDIM, NDIM]
         const float* __restrict__ bias,  // [NE, NDIM]
         float* __restrict__ C)           // row = token id, width NDIM
{
    int e = blockIdx.z;
    int cnt = g_cnt[e];
    int mstart = blockIdx.y * 128;
    if (mstart >= cnt) return;
    int n0 = blockIdx.x * 128;
    const float* Be = B + (size_t)e * KDIM * NDIM;

    __shared__ float As[8][132];   // padded: kills 2-way store conflicts
    __shared__ float Bs[8][128];
    __shared__ int   toks[128];
    __shared__ float gw[128];

    int tid = threadIdx.x;
    if (tid < 128) {
        int r = mstart + tid;
        int tok = (r < cnt) ? g_list[e][r] : -1;
        toks[tid] = tok;
        if (!GELU) {
            float g = 0.0f;
            if (tok >= 0) g = g_score[tok] * CAPF / (g_colsum[e] + GEPS);
            gw[tid] = g;
        }
    }
    __syncthreads();

    // A loader: 128 rows x 8 k per tile; one float4 per thread
    int arow = tid >> 1;
    int akq  = (tid & 1) * 4;
    int atok = toks[arow];
    const float* aptr = (atok >= 0) ? (A + (size_t)atok * KDIM + akq) : A;

    // B loader: 8 k x 128 n; one float4 per thread, fully coalesced
    int bk = tid >> 5;
    int bn = (tid & 31) * 4;
    const float* bptr = Be + (size_t)bk * NDIM + n0 + bn;

    int ty = tid >> 4, tx = tid & 15;

    float acc[8][8];
#pragma unroll
    for (int i = 0; i < 8; i++)
#pragma unroll
        for (int j = 0; j < 8; j++) acc[i][j] = 0.0f;

    for (int k0 = 0; k0 < KDIM; k0 += 8) {
        float4 av = make_float4(0.f, 0.f, 0.f, 0.f);
        if (atok >= 0) av = *(const float4*)(aptr + k0);
        float4 bv = *(const float4*)(bptr + (size_t)k0 * NDIM);
        As[akq + 0][arow] = av.x;
        As[akq + 1][arow] = av.y;
        As[akq + 2][arow] = av.z;
        As[akq + 3][arow] = av.w;
        *(float4*)&Bs[bk][bn] = bv;
        __syncthreads();
#pragma unroll
        for (int k = 0; k < 8; k++) {
            float4 a0 = *(const float4*)&As[k][ty * 8];
            float4 a1 = *(const float4*)&As[k][ty * 8 + 4];
            float4 b0 = *(const float4*)&Bs[k][tx * 8];
            float4 b1 = *(const float4*)&Bs[k][tx * 8 + 4];
            float am[8] = {a0.x, a0.y, a0.z, a0.w, a1.x, a1.y, a1.z, a1.w};
            float bm[8] = {b0.x, b0.y, b0.z, b0.w, b1.x, b1.y, b1.z, b1.w};
#pragma unroll
            for (int i = 0; i < 8; i++)
#pragma unroll
                for (int j = 0; j < 8; j++)
                    acc[i][j] = fmaf(am[i], bm[j], acc[i][j]);
        }
        __syncthreads();
    }

    const float* be = bias + (size_t)e * NDIM + n0 + tx * 8;
#pragma unroll
    for (int i = 0; i < 8; i++) {
        int row = ty * 8 + i;
        int tok = toks[row];
        if (tok < 0) continue;
        float* crow = C + (size_t)tok * NDIM + n0 + tx * 8;
        if (GELU) {
#pragma unroll
            for (int j = 0; j < 8; j++) {
                float c = acc[i][j] + be[j];
                float sgm = 1.0f / (1.0f + expf(-1.702f * c));
                crow[j] = c * sgm;
            }
        } else {
            float g = gw[row];
#pragma unroll
            for (int j = 0; j < 8; j++) {
                float c = acc[i][j] + be[j];
                crow[j] = c * g;
            }
        }
    }
}

extern "C" void kernel_launch(void* const* d_in, const int* in_sizes, int n_in,
                              void* d_out, int out_size) {
    const float* x  = (const float*)d_in[0];
    const float* wg = (const float*)d_in[1];
    const float* bg = (const float*)d_in[2];
    const float* w1 = (const float*)d_in[3];
    const float* b1 = (const float*)d_in[4];
    const float* w2 = (const float*)d_in[5];
    const float* b2 = (const float*)d_in[6];
    float* out = (float*)d_out;

    init_kernel<<<1, 32>>>();
    gate_kernel<<<(NT * 32 + 255) / 256, 256>>>(x, wg, bg);
    colsum_kernel<<<NE, 256>>>();
    loss_kernel<<<1, 32>>>(out, out_size - 1);
    // GEMM1: H = gelu(x @ w1[e] + b1[e]), gathered per expert
    ffn_gemm<D, HD, true><<<dim3(HD / 128, NT / 128, NE), 256>>>(x, w1, b1, g_H);
    // GEMM2: out[tok] = (H @ w2[e] + b2[e]) * gate, scattered by token id
    ffn_gemm<HD, D, false><<<dim3(D / 128, NT / 128, NE), 256>>>(g_H, w2, b2, out);
}

// round 3
// speedup vs baseline: 1.5871x; 1.5871x over previous
#include <cuda_runtime.h>
#include <math.h>

// Problem constants
static constexpr int NT  = 4096;
static constexpr int D   = 1024;
static constexpr int HD  = 4096;
static constexpr int NE  = 8;
static constexpr float CAPF = 4096.0f;
static constexpr float GEPS = 1e-6f;

// Scratch
__device__ int   g_expert[NT];
__device__ float g_score[NT];
__device__ int   g_cnt[NE];
__device__ int   g_list[NE][NT];
__device__ float g_colsum[NE];
__device__ float g_H[(size_t)NT * HD];   // 64 MB hidden activations (fp32)

__global__ void init_kernel() {
    int t = threadIdx.x;
    if (t < NE) { g_cnt[t] = 0; g_colsum[t] = 0.0f; }
}

__global__ void gate_kernel(const float* __restrict__ x,
                            const float* __restrict__ wg,
                            const float* __restrict__ bg) {
    int tok  = (blockIdx.x * blockDim.x + threadIdx.x) >> 5;
    int lane = threadIdx.x & 31;
    if (tok >= NT) return;
    const float* xr = x + (size_t)tok * D;
    float acc[NE];
#pragma unroll
    for (int e = 0; e < NE; e++) acc[e] = 0.0f;
    for (int i = lane; i < D; i += 32) {
        float xv = xr[i];
        const float* wr = wg + (size_t)i * NE;
#pragma unroll
        for (int e = 0; e < NE; e++) acc[e] = fmaf(xv, wr[e], acc[e]);
    }
#pragma unroll
    for (int off = 16; off; off >>= 1) {
#pragma unroll
        for (int e = 0; e < NE; e++)
            acc[e] += __shfl_xor_sync(0xffffffffu, acc[e], off);
    }
    if (lane == 0) {
        float l[NE];
        l[0] = acc[0] + bg[0];
        float m = l[0]; int a = 0;
#pragma unroll
        for (int e = 1; e < NE; e++) {
            l[e] = acc[e] + bg[e];
            if (l[e] > m) { m = l[e]; a = e; }
        }
        float s = 0.0f;
#pragma unroll
        for (int e = 0; e < NE; e++) s += expf(l[e] - m);
        float p = 1.0f / s;
        g_expert[tok] = a;
        g_score[tok]  = p;
        int pos = atomicAdd(&g_cnt[a], 1);
        g_list[a][pos] = tok;
    }
}

__global__ void colsum_kernel() {
    __shared__ float red[256];
    int e = blockIdx.x;
    float s = 0.0f;
    for (int n = threadIdx.x; n < NT; n += 256)
        if (g_expert[n] == e) s += g_score[n];
    red[threadIdx.x] = s;
    __syncthreads();
    for (int o = 128; o; o >>= 1) {
        if (threadIdx.x < o) red[threadIdx.x] += red[threadIdx.x + o];
        __syncthreads();
    }
    if (threadIdx.x == 0) g_colsum[e] = red[0];
}

__global__ void loss_kernel(float* __restrict__ out, int loss_idx) {
    if (threadIdx.x == 0 && blockIdx.x == 0) {
        float load[NE];
        float tot = 0.0f;
#pragma unroll
        for (int e = 0; e < NE; e++) {
            float c = g_colsum[e];
            load[e] = c * CAPF / (c + GEPS);
            tot += load[e];
        }
        float imp = tot / (float)NT;
        float l = 0.0f;
#pragma unroll
        for (int e = 0; e < NE; e++) {
            float d = load[e] - imp;
            l += d * d;
        }
        out[loss_idx] = l / (float)NE;
    }
}

// ---- tensor-core FFN GEMM (tf32 mma.sync) ----

__device__ __forceinline__ unsigned f2tf(float f) {
    unsigned u;
    asm("cvt.rna.tf32.f32 %0, %1;" : "=r"(u) : "f"(f));
    return u;
}

__device__ __forceinline__ void mma8(float* c, const unsigned* a, const unsigned* b) {
    asm volatile(
        "mma.sync.aligned.m16n8k8.row.col.f32.tf32.tf32.f32 "
        "{%0,%1,%2,%3}, {%4,%5,%6,%7}, {%8,%9}, {%0,%1,%2,%3};"
        : "+f"(c[0]), "+f"(c[1]), "+f"(c[2]), "+f"(c[3])
        : "r"(a[0]), "r"(a[1]), "r"(a[2]), "r"(a[3]), "r"(b[0]), "r"(b[1]));
}

// CTA 128x128 tile, BK=32, 8 warps (2x4), warp tile 64x32.
// As[k][m], Bs[k][n], stride 136 -> conflict-free fragment LDS.
template <int KDIM, int NDIM, bool GELU>
__global__ void __launch_bounds__(256, 1)
ffn_mma(const float* __restrict__ A,
        const float* __restrict__ B,     // [NE, KDIM, NDIM]
        const float* __restrict__ bias,  // [NE, NDIM]
        float* __restrict__ C)           // row = token id
{
    int e = blockIdx.z;
    int cnt = g_cnt[e];
    int mstart = blockIdx.y * 128;
    if (mstart >= cnt) return;
    int n0 = blockIdx.x * 128;
    const float* Be = B + (size_t)e * KDIM * NDIM;

    __shared__ unsigned As[32][136];
    __shared__ unsigned Bs[32][136];
    __shared__ int   toks[128];
    __shared__ float gw[128];

    int tid = threadIdx.x;
    if (tid < 128) {
        int r = mstart + tid;
        int tok = (r < cnt) ? g_list[e][r] : -1;
        toks[tid] = tok;
        if (!GELU) {
            float g = 0.0f;
            if (tok >= 0) g = g_score[tok] * CAPF / (g_colsum[e] + GEPS);
            gw[tid] = g;
        }
    }
    __syncthreads();

    // A loader: row = tid&127, k-half = tid>>7 (16 k each => 4 float4)
    int arow  = tid & 127;
    int ahalf = (tid >> 7) * 16;
    int atok  = toks[arow];
    const float* aptr = A + (atok >= 0 ? (size_t)atok * KDIM : 0) + ahalf;

    // B loader: k-row = tid>>3, n-quad base = (tid&7)*4, 4 quads stride 32
    int bk = tid >> 3;
    int bq = (tid & 7) * 4;
    const float* bptr = Be + (size_t)bk * NDIM + n0 + bq;

    int wid = tid >> 5, lane = tid & 31;
    int wm = (wid & 1) * 64;
    int wn = (wid >> 1) * 32;
    int gid = lane >> 2, tig = lane & 3;

    float acc[4][4][4];
#pragma unroll
    for (int mi = 0; mi < 4; mi++)
#pragma unroll
        for (int ni = 0; ni < 4; ni++)
#pragma unroll
            for (int q = 0; q < 4; q++) acc[mi][ni][q] = 0.0f;

    float4 pa[4], pb[4];

    // prefetch tile 0
#pragma unroll
    for (int j = 0; j < 4; j++)
        pa[j] = (atok >= 0) ? *(const float4*)(aptr + j * 4)
                            : make_float4(0.f, 0.f, 0.f, 0.f);
#pragma unroll
    for (int j = 0; j < 4; j++)
        pb[j] = *(const float4*)(bptr + j * 32);

    constexpr int NIT = KDIM / 32;
    for (int it = 0; it < NIT; it++) {
        __syncthreads();   // previous compute finished reading smem
        // store prefetched tile (with tf32 rounding)
#pragma unroll
        for (int j = 0; j < 4; j++) {
            int k = ahalf + j * 4;
            As[k + 0][arow] = f2tf(pa[j].x);
            As[k + 1][arow] = f2tf(pa[j].y);
            As[k + 2][arow] = f2tf(pa[j].z);
            As[k + 3][arow] = f2tf(pa[j].w);
        }
#pragma unroll
        for (int j = 0; j < 4; j++) {
            unsigned* bs = &Bs[bk][bq + 32 * j];
            bs[0] = f2tf(pb[j].x);
            bs[1] = f2tf(pb[j].y);
            bs[2] = f2tf(pb[j].z);
            bs[3] = f2tf(pb[j].w);
        }
        __syncthreads();

        // issue next tile's global loads early (overlap with compute)
        if (it + 1 < NIT) {
            int k0 = (it + 1) * 32;
#pragma unroll
            for (int j = 0; j < 4; j++)
                pa[j] = (atok >= 0) ? *(const float4*)(aptr + k0 + j * 4)
                                    : make_float4(0.f, 0.f, 0.f, 0.f);
#pragma unroll
            for (int j = 0; j < 4; j++)
                pb[j] = *(const float4*)(bptr + (size_t)k0 * NDIM + j * 32);
        }

        // compute 4 k-steps of 8
#pragma unroll
        for (int ks = 0; ks < 4; ks++) {
            unsigned af[4][4], bf[4][2];
#pragma unroll
            for (int mi = 0; mi < 4; mi++) {
                int rm = wm + mi * 16 + gid;
                af[mi][0] = As[ks * 8 + tig][rm];
                af[mi][1] = As[ks * 8 + tig][rm + 8];
                af[mi][2] = As[ks * 8 + tig + 4][rm];
                af[mi][3] = As[ks * 8 + tig + 4][rm + 8];
            }
#pragma unroll
            for (int ni = 0; ni < 4; ni++) {
                int cn = wn + ni * 8 + gid;
                bf[ni][0] = Bs[ks * 8 + tig][cn];
                bf[ni][1] = Bs[ks * 8 + tig + 4][cn];
            }
#pragma unroll
            for (int mi = 0; mi < 4; mi++)
#pragma unroll
                for (int ni = 0; ni < 4; ni++)
                    mma8(acc[mi][ni], af[mi], bf[ni]);
        }
    }

    // epilogue
    const float* be = bias + (size_t)e * NDIM + n0;
#pragma unroll
    for (int mi = 0; mi < 4; mi++) {
#pragma unroll
        for (int half = 0; half < 2; half++) {
            int lr = wm + mi * 16 + gid + half * 8;
            int tok = toks[lr];
            if (tok < 0) continue;
            float* crow = C + (size_t)tok * NDIM + n0;
            float g = GELU ? 0.0f : gw[lr];
#pragma unroll
            for (int ni = 0; ni < 4; ni++) {
                int cn = wn + ni * 8 + tig * 2;
                float v0 = acc[mi][ni][half * 2 + 0] + __ldg(be + cn);
                float v1 = acc[mi][ni][half * 2 + 1] + __ldg(be + cn + 1);
                if (GELU) {
                    v0 = v0 / (1.0f + expf(-1.702f * v0));
                    v1 = v1 / (1.0f + expf(-1.702f * v1));
                } else {
                    v0 *= g;
                    v1 *= g;
                }
                *(float2*)(crow + cn) = make_float2(v0, v1);
            }
        }
    }
}

extern "C" void kernel_launch(void* const* d_in, const int* in_sizes, int n_in,
                              void* d_out, int out_size) {
    const float* x  = (const float*)d_in[0];
    const float* wg = (const float*)d_in[1];
    const float* bg = (const float*)d_in[2];
    const float* w1 = (const float*)d_in[3];
    const float* b1 = (const float*)d_in[4];
    const float* w2 = (const float*)d_in[5];
    const float* b2 = (const float*)d_in[6];
    float* out = (float*)d_out;

    init_kernel<<<1, 32>>>();
    gate_kernel<<<(NT * 32 + 255) / 256, 256>>>(x, wg, bg);
    colsum_kernel<<<NE, 256>>>();
    loss_kernel<<<1, 32>>>(out, out_size - 1);
    ffn_mma<D, HD, true><<<dim3(HD / 128, NT / 128, NE), 256>>>(x, w1, b1, g_H);
    ffn_mma<HD, D, false><<<dim3(D / 128, NT / 128, NE), 256>>>(g_H, w2, b2, out);
}

// round 9
// speedup vs baseline: 6.9437x; 4.3751x over previous
#include <cuda_runtime.h>
#include <cuda_bf16.h>
#include <math.h>
#include <stdint.h>

// Problem constants
static constexpr int NT  = 4096;
static constexpr int D   = 1024;
static constexpr int HD  = 4096;
static constexpr int NE  = 8;
static constexpr float CAPF = 4096.0f;
static constexpr float GEPS = 1e-6f;

// ---------------- device scratch ----------------
__device__ int   g_expert[NT];
__device__ float g_score[NT];
__device__ int   g_cnt[NE];
__device__ int   g_list[NE][NT];
__device__ float g_colsum[NE];

// hi/lo bf16 splits (layouts unchanged: weights [e][k][n], acts [row][col])
__device__ __nv_bfloat16 g_Xhi[(size_t)NT * D];
__device__ __nv_bfloat16 g_Xlo[(size_t)NT * D];
__device__ __nv_bfloat16 g_w1hi[(size_t)NE * D * HD];
__device__ __nv_bfloat16 g_w1lo[(size_t)NE * D * HD];
__device__ __nv_bfloat16 g_w2hi[(size_t)NE * HD * D];
__device__ __nv_bfloat16 g_w2lo[(size_t)NE * HD * D];
__device__ __nv_bfloat16 g_Hhi[(size_t)NT * HD];
__device__ __nv_bfloat16 g_Hlo[(size_t)NT * HD];

// ---------------- helpers ----------------
__device__ __forceinline__ void split2(float a, float b, uint32_t& hp, uint32_t& lp) {
    __nv_bfloat16 ha = __float2bfloat16(a);
    __nv_bfloat16 hb = __float2bfloat16(b);
    __nv_bfloat16 la = __float2bfloat16(a - __bfloat162float(ha));
    __nv_bfloat16 lb = __float2bfloat16(b - __bfloat162float(hb));
    hp = ((uint32_t)__bfloat16_as_ushort(hb) << 16) | __bfloat16_as_ushort(ha);
    lp = ((uint32_t)__bfloat16_as_ushort(lb) << 16) | __bfloat16_as_ushort(la);
}

__device__ __forceinline__ void mma16816(float* c, const uint32_t* a, uint32_t b0, uint32_t b1) {
    asm volatile(
        "mma.sync.aligned.m16n8k16.row.col.f32.bf16.bf16.f32 "
        "{%0,%1,%2,%3}, {%4,%5,%6,%7}, {%8,%9}, {%0,%1,%2,%3};"
        : "+f"(c[0]), "+f"(c[1]), "+f"(c[2]), "+f"(c[3])
        : "r"(a[0]), "r"(a[1]), "r"(a[2]), "r"(a[3]), "r"(b0), "r"(b1));
}

// ---------------- small kernels (proven in R3) ----------------
__global__ void init_kernel() {
    int t = threadIdx.x;
    if (t < NE) { g_cnt[t] = 0; g_colsum[t] = 0.0f; }
}

__global__ void gate_kernel(const float* __restrict__ x,
                            const float* __restrict__ wg,
                            const float* __restrict__ bg) {
    int tok  = (blockIdx.x * blockDim.x + threadIdx.x) >> 5;
    int lane = threadIdx.x & 31;
    if (tok >= NT) return;
    const float* xr = x + (size_t)tok * D;
    float acc[NE];
#pragma unroll
    for (int e = 0; e < NE; e++) acc[e] = 0.0f;
    for (int i = lane; i < D; i += 32) {
        float xv = xr[i];
        const float* wr = wg + (size_t)i * NE;
#pragma unroll
        for (int e = 0; e < NE; e++) acc[e] = fmaf(xv, wr[e], acc[e]);
    }
#pragma unroll
    for (int off = 16; off; off >>= 1)
#pragma unroll
        for (int e = 0; e < NE; e++)
            acc[e] += __shfl_xor_sync(0xffffffffu, acc[e], off);
    if (lane == 0) {
        float l[NE];
        l[0] = acc[0] + bg[0];
        float m = l[0]; int a = 0;
#pragma unroll
        for (int e = 1; e < NE; e++) {
            l[e] = acc[e] + bg[e];
            if (l[e] > m) { m = l[e]; a = e; }
        }
        float s = 0.0f;
#pragma unroll
        for (int e = 0; e < NE; e++) s += expf(l[e] - m);
        g_expert[tok] = a;
        g_score[tok]  = 1.0f / s;
        int pos = atomicAdd(&g_cnt[a], 1);
        g_list[a][pos] = tok;
    }
}

__global__ void colsum_kernel() {
    __shared__ float red[256];
    int e = blockIdx.x;
    float s = 0.0f;
    for (int n = threadIdx.x; n < NT; n += 256)
        if (g_expert[n] == e) s += g_score[n];
    red[threadIdx.x] = s;
    __syncthreads();
    for (int o = 128; o; o >>= 1) {
        if (threadIdx.x < o) red[threadIdx.x] += red[threadIdx.x + o];
        __syncthreads();
    }
    if (threadIdx.x == 0) g_colsum[e] = red[0];
}

__global__ void loss_kernel(float* __restrict__ out, int loss_idx) {
    if (threadIdx.x == 0 && blockIdx.x == 0) {
        float load[NE], tot = 0.0f;
#pragma unroll
        for (int e = 0; e < NE; e++) {
            float c = g_colsum[e];
            load[e] = c * CAPF / (c + GEPS);
            tot += load[e];
        }
        float imp = tot / (float)NT;
        float l = 0.0f;
#pragma unroll
        for (int e = 0; e < NE; e++) { float d = load[e] - imp; l += d * d; }
        out[loss_idx] = l / (float)NE;
    }
}

// elementwise fp32 -> bf16 hi/lo split (layout preserved)
// NOTE: hi/lo MUST be real device pointers (resolved via cudaGetSymbolAddress).
__global__ void __launch_bounds__(256)
split_kernel(const float* __restrict__ src,
             __nv_bfloat16* __restrict__ hi,
             __nv_bfloat16* __restrict__ lo, int npairs) {
    int i = blockIdx.x * 256 + threadIdx.x;
    if (i >= npairs) return;
    float2 v = ((const float2*)src)[i];
    uint32_t hp, lp;
    split2(v.x, v.y, hp, lp);
    ((uint32_t*)hi)[i] = hp;
    ((uint32_t*)lo)[i] = lp;
}

// ---------------- bf16-split tensor GEMM (R3-style data movement) ----------------
// CTA 128m x 128n, BK=32, single smem buffer + register prefetch, 8 warps (2m x 4n).
// As [m][k]: 128 rows x 16 words data, stride 20 words (conflict-free frags).
// Bs [kpair][n]: 16 rows x 128 words, stride 136 words (conflict-free frags).
// acc = Ahi*Bhi + Alo*Bhi + Ahi*Blo  (fp32 accum in registers)
static constexpr int AST = 20;    // A row stride in words
static constexpr int BST = 136;   // B row stride in words

template <int KDIM, int NDIM, bool GELU>
__global__ void __launch_bounds__(256, 1)
ffn_bf16(const float* __restrict__ bias,  // [NE][NDIM]
         float* __restrict__ out) {
    __shared__ uint32_t As_h[128 * AST], As_l[128 * AST];
    __shared__ uint32_t Bs_h[16 * BST],  Bs_l[16 * BST];
    __shared__ int   toks[128];
    __shared__ float gw[128];

    int e = blockIdx.z;
    int cnt = g_cnt[e];
    int mstart = blockIdx.y * 128;
    if (mstart >= cnt) return;
    int n0 = blockIdx.x * 128;

    int tid = threadIdx.x;
    int wid = tid >> 5, lane = tid & 31;

    if (tid < 128) {
        int rr = mstart + tid;
        int tok = (rr < cnt) ? g_list[e][rr] : -1;
        toks[tid] = tok;
        if (!GELU) {
            float g = 0.0f;
            if (tok >= 0) g = g_score[tok] * CAPF / (g_colsum[e] + GEPS);
            gw[tid] = g;
        }
    }
    __syncthreads();

    // device-side references to device globals (correct addresses)
    const __nv_bfloat16* Ah = GELU ? g_Xhi : g_Hhi;
    const __nv_bfloat16* Al = GELU ? g_Xlo : g_Hlo;
    const __nv_bfloat16* Wh = GELU ? g_w1hi : g_w2hi;
    const __nv_bfloat16* Wl = GELU ? g_w1lo : g_w2lo;

    // ---- loader assignments ----
    // A: thread t -> row r = t>>1, 32B half h = t&1 (k words h*8 .. h*8+7)
    int ar = tid >> 1;
    int ahalf = tid & 1;
    int atok = toks[ar];
    const __nv_bfloat16* ah_p = Ah + (size_t)(atok >= 0 ? atok : 0) * KDIM + ahalf * 16;
    const __nv_bfloat16* al_p = Al + (size_t)(atok >= 0 ? atok : 0) * KDIM + ahalf * 16;
    uint32_t a_sts = (uint32_t)(ar * AST + ahalf * 8);

    // B: thread t -> kpair kp = t>>4 (0..15), col block nb8 = (t&15)*8
    int kp = tid >> 4;
    int nb8 = (tid & 15) * 8;
    const __nv_bfloat16* bh_p = Wh + ((size_t)e * KDIM + 2 * kp) * NDIM + n0 + nb8;
    const __nv_bfloat16* bl_p = Wl + ((size_t)e * KDIM + 2 * kp) * NDIM + n0 + nb8;
    uint32_t b_sts = (uint32_t)(kp * BST + nb8);

    // warp tile coords
    int wm = (wid & 1) * 64;
    int wn = (wid >> 1) * 32;
    int gid = lane >> 2, tig = lane & 3;

    float acc[4][4][4];
#pragma unroll
    for (int mb = 0; mb < 4; mb++)
#pragma unroll
        for (int nb = 0; nb < 4; nb++)
#pragma unroll
            for (int q = 0; q < 4; q++) acc[mb][nb][q] = 0.0f;

    constexpr int NIT = KDIM / 32;
    uint4 pah0, pah1, pal0, pal1;      // A prefetch (hi/lo, 2 chunks each)
    uint4 pbh0, pbh1, pbl0, pbl1;      // B prefetch (rows 2kp, 2kp+1)
    const uint4 Z = make_uint4(0, 0, 0, 0);

    auto load8 = [&](int it) {
        size_t ao = (size_t)it * 32;
        if (atok >= 0) {
            pah0 = *(const uint4*)(ah_p + ao);
            pah1 = *(const uint4*)(ah_p + ao + 8);
            pal0 = *(const uint4*)(al_p + ao);
            pal1 = *(const uint4*)(al_p + ao + 8);
        } else {
            pah0 = Z; pah1 = Z; pal0 = Z; pal1 = Z;
        }
        size_t bo = (size_t)it * 32 * NDIM;
        pbh0 = *(const uint4*)(bh_p + bo);
        pbh1 = *(const uint4*)(bh_p + bo + NDIM);
        pbl0 = *(const uint4*)(bl_p + bo);
        pbl1 = *(const uint4*)(bl_p + bo + NDIM);
    };

    auto store8 = [&]() {
        *(uint4*)&As_h[a_sts]     = pah0;
        *(uint4*)&As_h[a_sts + 4] = pah1;
        *(uint4*)&As_l[a_sts]     = pal0;
        *(uint4*)&As_l[a_sts + 4] = pal1;
        uint4 w;
        // hi: pack k-pairs (low half = even k)
        w.x = __byte_perm(pbh0.x, pbh1.x, 0x5410);
        w.y = __byte_perm(pbh0.x, pbh1.x, 0x7632);
        w.z = __byte_perm(pbh0.y, pbh1.y, 0x5410);
        w.w = __byte_perm(pbh0.y, pbh1.y, 0x7632);
        *(uint4*)&Bs_h[b_sts] = w;
        w.x = __byte_perm(pbh0.z, pbh1.z, 0x5410);
        w.y = __byte_perm(pbh0.z, pbh1.z, 0x7632);
        w.z = __byte_perm(pbh0.w, pbh1.w, 0x5410);
        w.w = __byte_perm(pbh0.w, pbh1.w, 0x7632);
        *(uint4*)&Bs_h[b_sts + 4] = w;
        // lo
        w.x = __byte_perm(pbl0.x, pbl1.x, 0x5410);
        w.y = __byte_perm(pbl0.x, pbl1.x, 0x7632);
        w.z = __byte_perm(pbl0.y, pbl1.y, 0x5410);
        w.w = __byte_perm(pbl0.y, pbl1.y, 0x7632);
        *(uint4*)&Bs_l[b_sts] = w;
        w.x = __byte_perm(pbl0.z, pbl1.z, 0x5410);
        w.y = __byte_perm(pbl0.z, pbl1.z, 0x7632);
        w.z = __byte_perm(pbl0.w, pbl1.w, 0x5410);
        w.w = __byte_perm(pbl0.w, pbl1.w, 0x7632);
        *(uint4*)&Bs_l[b_sts + 4] = w;
    };

    load8(0);
    for (int it = 0; it < NIT; it++) {
        __syncthreads();   // previous compute done reading smem
        store8();
        __syncthreads();
        if (it + 1 < NIT) load8(it + 1);   // overlap next gmem loads with compute

#pragma unroll
        for (int ks = 0; ks < 2; ks++) {
            uint32_t ah[4][4], al[4][4];
#pragma unroll
            for (int mb = 0; mb < 4; mb++) {
                int base = (wm + mb * 16 + gid) * AST + ks * 8 + tig;
                ah[mb][0] = As_h[base];
                ah[mb][1] = As_h[base + 8 * AST];
                ah[mb][2] = As_h[base + 4];
                ah[mb][3] = As_h[base + 8 * AST + 4];
                al[mb][0] = As_l[base];
                al[mb][1] = As_l[base + 8 * AST];
                al[mb][2] = As_l[base + 4];
                al[mb][3] = As_l[base + 8 * AST + 4];
            }
            uint32_t bh[4][2], bl[4][2];
#pragma unroll
            for (int nb = 0; nb < 4; nb++) {
                int base = (ks * 8 + tig) * BST + wn + nb * 8 + gid;
                bh[nb][0] = Bs_h[base];
                bh[nb][1] = Bs_h[base + 4 * BST];
                bl[nb][0] = Bs_l[base];
                bl[nb][1] = Bs_l[base + 4 * BST];
            }
#pragma unroll
            for (int mb = 0; mb < 4; mb++)
#pragma unroll
                for (int nb = 0; nb < 4; nb++) {
                    mma16816(acc[mb][nb], ah[mb], bh[nb][0], bh[nb][1]);
                    mma16816(acc[mb][nb], al[mb], bh[nb][0], bh[nb][1]);
                    mma16816(acc[mb][nb], ah[mb], bl[nb][0], bl[nb][1]);
                }
        }
    }

    // ---- epilogue ----
    const float* be = bias + (size_t)e * NDIM + n0;
#pragma unroll
    for (int mb = 0; mb < 4; mb++) {
#pragma unroll
        for (int half = 0; half < 2; half++) {
            int rm = wm + mb * 16 + gid + half * 8;
            int tok = toks[rm];
            if (tok < 0) continue;
#pragma unroll
            for (int nb = 0; nb < 4; nb++) {
                int cn = wn + nb * 8 + 2 * tig;
                float v0 = acc[mb][nb][half * 2 + 0] + __ldg(be + cn);
                float v1 = acc[mb][nb][half * 2 + 1] + __ldg(be + cn + 1);
                if (GELU) {
                    v0 = v0 / (1.0f + expf(-1.702f * v0));
                    v1 = v1 / (1.0f + expf(-1.702f * v1));
                    uint32_t hp, lp;
                    split2(v0, v1, hp, lp);
                    size_t o = ((size_t)tok * NDIM + n0 + cn) >> 1;
                    ((uint32_t*)g_Hhi)[o] = hp;
                    ((uint32_t*)g_Hlo)[o] = lp;
                } else {
                    float g = gw[rm];
                    *(float2*)(out + (size_t)tok * NDIM + n0 + cn) =
                        make_float2(v0 * g, v1 * g);
                }
            }
        }
    }
}

// ---------------- launch ----------------
extern "C" void kernel_launch(void* const* d_in, const int* in_sizes, int n_in,
                              void* d_out, int out_size) {
    const float* x  = (const float*)d_in[0];
    const float* wg = (const float*)d_in[1];
    const float* bg = (const float*)d_in[2];
    const float* w1 = (const float*)d_in[3];
    const float* b1 = (const float*)d_in[4];
    const float* w2 = (const float*)d_in[5];
    const float* b2 = (const float*)d_in[6];
    float* out = (float*)d_out;

    // Resolve REAL device addresses of the __device__ globals for kernel args.
    // (Passing the symbol name from host code passes the host shadow address —
    //  that was the R5/R6 bug: splits wrote nowhere, GEMMs read zeros.)
    __nv_bfloat16 *xh, *xl, *w1h, *w1l, *w2h, *w2l;
    cudaGetSymbolAddress((void**)&xh,  g_Xhi);
    cudaGetSymbolAddress((void**)&xl,  g_Xlo);
    cudaGetSymbolAddress((void**)&w1h, g_w1hi);
    cudaGetSymbolAddress((void**)&w1l, g_w1lo);
    cudaGetSymbolAddress((void**)&w2h, g_w2hi);
    cudaGetSymbolAddress((void**)&w2l, g_w2lo);

    init_kernel<<<1, 32>>>();
    gate_kernel<<<(NT * 32 + 255) / 256, 256>>>(x, wg, bg);
    colsum_kernel<<<NE, 256>>>();
    loss_kernel<<<1, 32>>>(out, out_size - 1);

    // fp32 -> bf16 hi/lo splits (now with real device pointers)
    split_kernel<<<(NT * D / 2 + 255) / 256, 256>>>(x, xh, xl, NT * D / 2);
    split_kernel<<<(NE * D * HD / 2 + 255) / 256, 256>>>(w1, w1h, w1l, NE * D * HD / 2);
    split_kernel<<<(NE * HD * D / 2 + 255) / 256, 256>>>(w2, w2h, w2l, NE * HD * D / 2);

    // GEMM1: H = gelu(x @ w1 + b1) -> g_Hhi/g_Hlo
    ffn_bf16<D, HD, true><<<dim3(HD / 128, NT / 128, NE), 256>>>(b1, nullptr);
    // GEMM2: out = (H @ w2 + b2) * gate
    ffn_bf16<HD, D, false><<<dim3(D / 128, NT / 128, NE), 256>>>(b2, out);
}

// round 10
// speedup vs baseline: 10.7321x; 1.5456x over previous
#include <cuda_runtime.h>
#include <cuda_fp16.h>
#include <math.h>
#include <stdint.h>

// Problem constants
static constexpr int NT  = 4096;
static constexpr int D   = 1024;
static constexpr int HD  = 4096;
static constexpr int NE  = 8;
static constexpr float CAPF = 4096.0f;
static constexpr float GEPS = 1e-6f;

// ---------------- device scratch ----------------
__device__ int   g_expert[NT];
__device__ float g_score[NT];
__device__ int   g_cnt[NE];
__device__ int   g_list[NE][NT];
__device__ float g_colsum[NE];
__device__ __half g_H[(size_t)NT * HD];   // hidden activations, fp16

// ---------------- helpers ----------------
__device__ __forceinline__ uint32_t pack_h2(float a, float b) {
    __half2 h = __floats2half2_rn(a, b);   // a -> low half
    return *reinterpret_cast<uint32_t*>(&h);
}

__device__ __forceinline__ void mma16816f(float* c, const uint32_t* a, uint32_t b0, uint32_t b1) {
    asm volatile(
        "mma.sync.aligned.m16n8k16.row.col.f32.f16.f16.f32 "
        "{%0,%1,%2,%3}, {%4,%5,%6,%7}, {%8,%9}, {%0,%1,%2,%3};"
        : "+f"(c[0]), "+f"(c[1]), "+f"(c[2]), "+f"(c[3])
        : "r"(a[0]), "r"(a[1]), "r"(a[2]), "r"(a[3]), "r"(b0), "r"(b1));
}

// ---------------- small kernels (proven) ----------------
__global__ void init_kernel() {
    int t = threadIdx.x;
    if (t < NE) { g_cnt[t] = 0; g_colsum[t] = 0.0f; }
}

__global__ void gate_kernel(const float* __restrict__ x,
                            const float* __restrict__ wg,
                            const float* __restrict__ bg) {
    int tok  = (blockIdx.x * blockDim.x + threadIdx.x) >> 5;
    int lane = threadIdx.x & 31;
    if (tok >= NT) return;
    const float* xr = x + (size_t)tok * D;
    float acc[NE];
#pragma unroll
    for (int e = 0; e < NE; e++) acc[e] = 0.0f;
    for (int i = lane; i < D; i += 32) {
        float xv = xr[i];
        const float* wr = wg + (size_t)i * NE;
#pragma unroll
        for (int e = 0; e < NE; e++) acc[e] = fmaf(xv, wr[e], acc[e]);
    }
#pragma unroll
    for (int off = 16; off; off >>= 1)
#pragma unroll
        for (int e = 0; e < NE; e++)
            acc[e] += __shfl_xor_sync(0xffffffffu, acc[e], off);
    if (lane == 0) {
        float l[NE];
        l[0] = acc[0] + bg[0];
        float m = l[0]; int a = 0;
#pragma unroll
        for (int e = 1; e < NE; e++) {
            l[e] = acc[e] + bg[e];
            if (l[e] > m) { m = l[e]; a = e; }
        }
        float s = 0.0f;
#pragma unroll
        for (int e = 0; e < NE; e++) s += expf(l[e] - m);
        g_expert[tok] = a;
        g_score[tok]  = 1.0f / s;
        int pos = atomicAdd(&g_cnt[a], 1);
        g_list[a][pos] = tok;
    }
}

__global__ void colsum_kernel() {
    __shared__ float red[256];
    int e = blockIdx.x;
    float s = 0.0f;
    for (int n = threadIdx.x; n < NT; n += 256)
        if (g_expert[n] == e) s += g_score[n];
    red[threadIdx.x] = s;
    __syncthreads();
    for (int o = 128; o; o >>= 1) {
        if (threadIdx.x < o) red[threadIdx.x] += red[threadIdx.x + o];
        __syncthreads();
    }
    if (threadIdx.x == 0) g_colsum[e] = red[0];
}

__global__ void loss_kernel(float* __restrict__ out, int loss_idx) {
    if (threadIdx.x == 0 && blockIdx.x == 0) {
        float load[NE], tot = 0.0f;
#pragma unroll
        for (int e = 0; e < NE; e++) {
            float c = g_colsum[e];
            load[e] = c * CAPF / (c + GEPS);
            tot += load[e];
        }
        float imp = tot / (float)NT;
        float l = 0.0f;
#pragma unroll
        for (int e = 0; e < NE; e++) { float d = load[e] - imp; l += d * d; }
        out[loss_idx] = l / (float)NE;
    }
}

// ---------------- fp16 tensor GEMM, fused fp32->fp16 conversion ----------------
// CTA 128m x 128n, BK=32, double-buffered smem, 8 warps (2m x 4n), warp 64x32.
// As [m][k-pairs]: stride 20 words; Bs [kpair][n]: stride 136 words (conflict-free).
static constexpr int AST = 20;
static constexpr int BST = 136;

template <int KDIM, int NDIM, bool GELU>
__global__ void __launch_bounds__(256, 1)
ffn_fp16(const float* __restrict__ xA,   // GEMM1: fp32 activations (ignored for GEMM2)
         const float* __restrict__ W,    // [NE][KDIM][NDIM] fp32 weights
         const float* __restrict__ bias, // [NE][NDIM]
         float* __restrict__ out) {
    __shared__ uint32_t As[2][128 * AST];
    __shared__ uint32_t Bs[2][16 * BST];
    __shared__ int   toks[128];
    __shared__ float gw[128];

    int e = blockIdx.z;
    int cnt = g_cnt[e];
    int mstart = blockIdx.y * 128;
    if (mstart >= cnt) return;
    int n0 = blockIdx.x * 128;

    int tid = threadIdx.x;
    int wid = tid >> 5, lane = tid & 31;

    if (tid < 128) {
        int rr = mstart + tid;
        int tok = (rr < cnt) ? g_list[e][rr] : -1;
        toks[tid] = tok;
        if (!GELU) {
            float g = 0.0f;
            if (tok >= 0) g = g_score[tok] * CAPF / (g_colsum[e] + GEPS);
            gw[tid] = g;
        }
    }
    __syncthreads();

    // ---- loader assignments ----
    // A: thread t -> row r=t>>1, k-half h=t&1 (16 k values)
    int ar = tid >> 1;
    int ahalf = tid & 1;
    int atok = toks[ar];
    size_t arow = (size_t)(atok >= 0 ? atok : 0);
    const float*  ap32 = xA ? (xA + arow * KDIM + ahalf * 16) : nullptr;
    const __half* ap16 = g_H + arow * KDIM + ahalf * 16;
    uint32_t a_sts = (uint32_t)(ar * AST + ahalf * 8);

    // B: thread t -> kpair kp=t>>4 (0..15), col block nb8=(t&15)*8
    int kp = tid >> 4;
    int nb8 = (tid & 15) * 8;
    const float* bp = W + ((size_t)e * KDIM + 2 * kp) * NDIM + n0 + nb8;
    uint32_t b_sts = (uint32_t)(kp * BST + nb8);

    // warp tile coords
    int wm = (wid & 1) * 64;
    int wn = (wid >> 1) * 32;
    int gid = lane >> 2, tig = lane & 3;

    float acc[4][4][4];
#pragma unroll
    for (int mb = 0; mb < 4; mb++)
#pragma unroll
        for (int nb = 0; nb < 4; nb++)
#pragma unroll
            for (int q = 0; q < 4; q++) acc[mb][nb][q] = 0.0f;

    constexpr int NIT = KDIM / 32;

    // prefetch registers
    float4 pa[4];        // GEMM1: 16 fp32 A values
    uint4  qa[2];        // GEMM2: 16 fp16 A values
    float4 pb0[2], pb1[2];  // B rows 2kp, 2kp+1 (8 fp32 each)

    auto load = [&](int it) {
        if (GELU) {
            if (atok >= 0) {
                const float* p = ap32 + (size_t)it * 32;
#pragma unroll
                for (int j = 0; j < 4; j++) pa[j] = *(const float4*)(p + j * 4);
            } else {
#pragma unroll
                for (int j = 0; j < 4; j++) pa[j] = make_float4(0.f, 0.f, 0.f, 0.f);
            }
        } else {
            if (atok >= 0) {
                const __half* p = ap16 + (size_t)it * 32;
                qa[0] = *(const uint4*)(p);
                qa[1] = *(const uint4*)(p + 8);
            } else {
                qa[0] = make_uint4(0, 0, 0, 0);
                qa[1] = make_uint4(0, 0, 0, 0);
            }
        }
        const float* pB = bp + (size_t)it * 32 * NDIM;
        pb0[0] = *(const float4*)(pB);
        pb0[1] = *(const float4*)(pB + 4);
        pb1[0] = *(const float4*)(pB + NDIM);
        pb1[1] = *(const float4*)(pB + NDIM + 4);
    };

    auto sts = [&](int b) {
        if (GELU) {
            uint4 w0, w1;
            w0.x = pack_h2(pa[0].x, pa[0].y);
            w0.y = pack_h2(pa[0].z, pa[0].w);
            w0.z = pack_h2(pa[1].x, pa[1].y);
            w0.w = pack_h2(pa[1].z, pa[1].w);
            w1.x = pack_h2(pa[2].x, pa[2].y);
            w1.y = pack_h2(pa[2].z, pa[2].w);
            w1.z = pack_h2(pa[3].x, pa[3].y);
            w1.w = pack_h2(pa[3].z, pa[3].w);
            *(uint4*)&As[b][a_sts]     = w0;
            *(uint4*)&As[b][a_sts + 4] = w1;
        } else {
            *(uint4*)&As[b][a_sts]     = qa[0];
            *(uint4*)&As[b][a_sts + 4] = qa[1];
        }
        // B: pack k-pairs (low = even k row 2kp, high = row 2kp+1)
        uint4 v0, v1;
        v0.x = pack_h2(pb0[0].x, pb1[0].x);
        v0.y = pack_h2(pb0[0].y, pb1[0].y);
        v0.z = pack_h2(pb0[0].z, pb1[0].z);
        v0.w = pack_h2(pb0[0].w, pb1[0].w);
        v1.x = pack_h2(pb0[1].x, pb1[1].x);
        v1.y = pack_h2(pb0[1].y, pb1[1].y);
        v1.z = pack_h2(pb0[1].z, pb1[1].z);
        v1.w = pack_h2(pb0[1].w, pb1[1].w);
        *(uint4*)&Bs[b][b_sts]     = v0;
        *(uint4*)&Bs[b][b_sts + 4] = v1;
    };

    load(0);
    sts(0);
    __syncthreads();

    for (int it = 0; it < NIT; it++) {
        if (it + 1 < NIT) load(it + 1);
        int b = it & 1;

#pragma unroll
        for (int ks = 0; ks < 2; ks++) {
            uint32_t ah[4][4];
#pragma unroll
            for (int mb = 0; mb < 4; mb++) {
                int base = (wm + mb * 16 + gid) * AST + ks * 8 + tig;
                ah[mb][0] = As[b][base];
                ah[mb][1] = As[b][base + 8 * AST];
                ah[mb][2] = As[b][base + 4];
                ah[mb][3] = As[b][base + 8 * AST + 4];
            }
            uint32_t bh[4][2];
#pragma unroll
            for (int nb = 0; nb < 4; nb++) {
                int base = (ks * 8 + tig) * BST + wn + nb * 8 + gid;
                bh[nb][0] = Bs[b][base];
                bh[nb][1] = Bs[b][base + 4 * BST];
            }
#pragma unroll
            for (int mb = 0; mb < 4; mb++)
#pragma unroll
                for (int nb = 0; nb < 4; nb++)
                    mma16816f(acc[mb][nb], ah[mb], bh[nb][0], bh[nb][1]);
        }

        if (it + 1 < NIT) sts((it + 1) & 1);
        __syncthreads();
    }

    // ---- epilogue ----
    const float* be = bias + (size_t)e * NDIM + n0;
#pragma unroll
    for (int mb = 0; mb < 4; mb++) {
#pragma unroll
        for (int half = 0; half < 2; half++) {
            int rm = wm + mb * 16 + gid + half * 8;
            int tok = toks[rm];
            if (tok < 0) continue;
#pragma unroll
            for (int nb = 0; nb < 4; nb++) {
                int cn = wn + nb * 8 + 2 * tig;
                float v0 = acc[mb][nb][half * 2 + 0] + __ldg(be + cn);
                float v1 = acc[mb][nb][half * 2 + 1] + __ldg(be + cn + 1);
                if (GELU) {
                    v0 = v0 / (1.0f + expf(-1.702f * v0));
                    v1 = v1 / (1.0f + expf(-1.702f * v1));
                    size_t o = ((size_t)tok * NDIM + n0 + cn) >> 1;
                    ((uint32_t*)g_H)[o] = pack_h2(v0, v1);
                } else {
                    float g = gw[rm];
                    *(float2*)(out + (size_t)tok * NDIM + n0 + cn) =
                        make_float2(v0 * g, v1 * g);
                }
            }
        }
    }
}

// ---------------- launch ----------------
extern "C" void kernel_launch(void* const* d_in, const int* in_sizes, int n_in,
                              void* d_out, int out_size) {
    const float* x  = (const float*)d_in[0];
    const float* wg = (const float*)d_in[1];
    const float* bg = (const float*)d_in[2];
    const float* w1 = (const float*)d_in[3];
    const float* b1 = (const float*)d_in[4];
    const float* w2 = (const float*)d_in[5];
    const float* b2 = (const float*)d_in[6];
    float* out = (float*)d_out;

    init_kernel<<<1, 32>>>();
    gate_kernel<<<(NT * 32 + 255) / 256, 256>>>(x, wg, bg);
    colsum_kernel<<<NE, 256>>>();
    loss_kernel<<<1, 32>>>(out, out_size - 1);

    // GEMM1: H = gelu(x @ w1 + b1) -> g_H (fp16), conversion fused into loaders
    ffn_fp16<D, HD, true><<<dim3(HD / 128, NT / 128, NE), 256>>>(x, w1, b1, nullptr);
    // GEMM2: out = (H @ w2 + b2) * gate
    ffn_fp16<HD, D, false><<<dim3(D / 128, NT / 128, NE), 256>>>(nullptr, w2, b2, out);
}

// round 11
// speedup vs baseline: 14.3943x; 1.3412x over previous
#include <cuda_runtime.h>
#include <cuda_fp16.h>
#include <math.h>
#include <stdint.h>

// Problem constants
static constexpr int NT  = 4096;
static constexpr int D   = 1024;
static constexpr int HD  = 4096;
static constexpr int NE  = 8;
static constexpr float CAPF = 4096.0f;
static constexpr float GEPS = 1e-6f;

// ---------------- device scratch ----------------
__device__ int   g_expert[NT];
__device__ float g_score[NT];
__device__ int   g_cnt[NE];
__device__ int   g_list[NE][NT];
__device__ float g_colsum[NE];
__device__ __half g_H[(size_t)NT * HD];                     // hidden acts, fp16
// k-pair-packed fp16 weights: word[(e*(K/2)+kp)*N + n] = (W[2kp][n] lo, W[2kp+1][n] hi)
__device__ uint32_t g_w1p[(size_t)NE * (D / 2) * HD];        // 64 MB
__device__ uint32_t g_w2p[(size_t)NE * (HD / 2) * D];        // 64 MB

// ---------------- helpers ----------------
__device__ __forceinline__ uint32_t pack_h2(float a, float b) {
    __half2 h = __floats2half2_rn(a, b);   // a -> low half
    return *reinterpret_cast<uint32_t*>(&h);
}

__device__ __forceinline__ void mma16816f(float* c, const uint32_t* a, uint32_t b0, uint32_t b1) {
    asm volatile(
        "mma.sync.aligned.m16n8k16.row.col.f32.f16.f16.f32 "
        "{%0,%1,%2,%3}, {%4,%5,%6,%7}, {%8,%9}, {%0,%1,%2,%3};"
        : "+f"(c[0]), "+f"(c[1]), "+f"(c[2]), "+f"(c[3])
        : "r"(a[0]), "r"(a[1]), "r"(a[2]), "r"(a[3]), "r"(b0), "r"(b1));
}

// ---------------- small kernels (proven) ----------------
__global__ void init_kernel() {
    int t = threadIdx.x;
    if (t < NE) { g_cnt[t] = 0; g_colsum[t] = 0.0f; }
}

__global__ void gate_kernel(const float* __restrict__ x,
                            const float* __restrict__ wg,
                            const float* __restrict__ bg) {
    int tok  = (blockIdx.x * blockDim.x + threadIdx.x) >> 5;
    int lane = threadIdx.x & 31;
    if (tok >= NT) return;
    const float* xr = x + (size_t)tok * D;
    float acc[NE];
#pragma unroll
    for (int e = 0; e < NE; e++) acc[e] = 0.0f;
    for (int i = lane; i < D; i += 32) {
        float xv = xr[i];
        const float* wr = wg + (size_t)i * NE;
#pragma unroll
        for (int e = 0; e < NE; e++) acc[e] = fmaf(xv, wr[e], acc[e]);
    }
#pragma unroll
    for (int off = 16; off; off >>= 1)
#pragma unroll
        for (int e = 0; e < NE; e++)
            acc[e] += __shfl_xor_sync(0xffffffffu, acc[e], off);
    if (lane == 0) {
        float l[NE];
        l[0] = acc[0] + bg[0];
        float m = l[0]; int a = 0;
#pragma unroll
        for (int e = 1; e < NE; e++) {
            l[e] = acc[e] + bg[e];
            if (l[e] > m) { m = l[e]; a = e; }
        }
        float s = 0.0f;
#pragma unroll
        for (int e = 0; e < NE; e++) s += expf(l[e] - m);
        g_expert[tok] = a;
        g_score[tok]  = 1.0f / s;
        int pos = atomicAdd(&g_cnt[a], 1);
        g_list[a][pos] = tok;
    }
}

__global__ void colsum_kernel() {
    __shared__ float red[256];
    int e = blockIdx.x;
    float s = 0.0f;
    for (int n = threadIdx.x; n < NT; n += 256)
        if (g_expert[n] == e) s += g_score[n];
    red[threadIdx.x] = s;
    __syncthreads();
    for (int o = 128; o; o >>= 1) {
        if (threadIdx.x < o) red[threadIdx.x] += red[threadIdx.x + o];
        __syncthreads();
    }
    if (threadIdx.x == 0) g_colsum[e] = red[0];
}

__global__ void loss_kernel(float* __restrict__ out, int loss_idx) {
    if (threadIdx.x == 0 && blockIdx.x == 0) {
        float load[NE], tot = 0.0f;
#pragma unroll
        for (int e = 0; e < NE; e++) {
            float c = g_colsum[e];
            load[e] = c * CAPF / (c + GEPS);
            tot += load[e];
        }
        float imp = tot / (float)NT;
        float l = 0.0f;
#pragma unroll
        for (int e = 0; e < NE; e++) { float d = load[e] - imp; l += d * d; }
        out[loss_idx] = l / (float)NE;
    }
}

// ---------------- weight pre-pack: fp32 [e][k][n] -> fp16 k-pair words ----------------
// word[(e*(K/2)+kp)*N + n] = half2(W[e][2kp][n], W[e][2kp+1][n])
template <int K, int N>
__global__ void __launch_bounds__(256)
prepack_kernel(const float* __restrict__ W, uint32_t* __restrict__ P) {
    int idx = blockIdx.x * 256 + threadIdx.x;          // one thread per 8 output words
    constexpr int N8 = N / 8;
    if (idx >= NE * (K / 2) * N8) return;
    int n8 = idx % N8;
    int kp = (idx / N8) % (K / 2);
    int e  = idx / (N8 * (K / 2));
    const float* r0 = W + ((size_t)e * K + 2 * kp) * N + n8 * 8;
    const float* r1 = r0 + N;
    float4 a0 = *(const float4*)(r0);
    float4 a1 = *(const float4*)(r0 + 4);
    float4 b0 = *(const float4*)(r1);
    float4 b1 = *(const float4*)(r1 + 4);
    uint4 w0, w1;
    w0.x = pack_h2(a0.x, b0.x);
    w0.y = pack_h2(a0.y, b0.y);
    w0.z = pack_h2(a0.z, b0.z);
    w0.w = pack_h2(a0.w, b0.w);
    w1.x = pack_h2(a1.x, b1.x);
    w1.y = pack_h2(a1.y, b1.y);
    w1.z = pack_h2(a1.z, b1.z);
    w1.w = pack_h2(a1.w, b1.w);
    uint32_t* dst = P + ((size_t)e * (K / 2) + kp) * N + n8 * 8;
    *(uint4*)(dst)     = w0;
    *(uint4*)(dst + 4) = w1;
}

// ---------------- fp16 tensor GEMM ----------------
// CTA 128m x 128n, BK=32, double-buffered smem, 8 warps (2m x 4n), warp 64x32.
// 2 CTAs/SM for latency overlap. B pre-packed fp16 (pure 16B copies).
static constexpr int AST = 20;
static constexpr int BST = 136;

template <int KDIM, int NDIM, bool GELU>
__global__ void __launch_bounds__(256, 2)
ffn_fp16(const float* __restrict__ xA,   // GEMM1: fp32 activations (null for GEMM2)
         const float* __restrict__ bias, // [NE][NDIM]
         float* __restrict__ out) {
    __shared__ uint32_t As[2][128 * AST];
    __shared__ uint32_t Bs[2][16 * BST];
    __shared__ int   toks[128];
    __shared__ float gw[128];

    int e = blockIdx.z;
    int cnt = g_cnt[e];
    int mstart = blockIdx.y * 128;
    if (mstart >= cnt) return;
    int n0 = blockIdx.x * 128;

    int tid = threadIdx.x;
    int wid = tid >> 5, lane = tid & 31;

    if (tid < 128) {
        int rr = mstart + tid;
        int tok = (rr < cnt) ? g_list[e][rr] : -1;
        toks[tid] = tok;
        if (!GELU) {
            float g = 0.0f;
            if (tok >= 0) g = g_score[tok] * CAPF / (g_colsum[e] + GEPS);
            gw[tid] = g;
        }
    }
    __syncthreads();

    // ---- loader assignments ----
    // A: thread t -> row r=t>>1, k-half h=t&1 (16 k values)
    int ar = tid >> 1;
    int ahalf = tid & 1;
    int atok = toks[ar];
    size_t arow = (size_t)(atok >= 0 ? atok : 0);
    const float*  ap32 = xA ? (xA + arow * KDIM + ahalf * 16) : nullptr;
    const __half* ap16 = g_H + arow * KDIM + ahalf * 16;
    uint32_t a_sts = (uint32_t)(ar * AST + ahalf * 8);

    // B: thread t -> kpair kp=t>>4 (0..15), col block nb8=(t&15)*8
    int kp = tid >> 4;
    int nb8 = (tid & 15) * 8;
    const uint32_t* Wp = GELU ? g_w1p : g_w2p;
    const uint32_t* bp = Wp + ((size_t)e * (KDIM / 2) + kp) * NDIM + n0 + nb8;
    uint32_t b_sts = (uint32_t)(kp * BST + nb8);

    // warp tile coords
    int wm = (wid & 1) * 64;
    int wn = (wid >> 1) * 32;
    int gid = lane >> 2, tig = lane & 3;

    float acc[4][4][4];
#pragma unroll
    for (int mb = 0; mb < 4; mb++)
#pragma unroll
        for (int nb = 0; nb < 4; nb++)
#pragma unroll
            for (int q = 0; q < 4; q++) acc[mb][nb][q] = 0.0f;

    constexpr int NIT = KDIM / 32;

    // prefetch registers
    float4 pa[4];        // GEMM1: 16 fp32 A values
    uint4  qa[2];        // GEMM2: 16 fp16 A values
    uint4  qb[2];        // 8 pre-packed B words

    auto load = [&](int it) {
        if (GELU) {
            if (atok >= 0) {
                const float* p = ap32 + (size_t)it * 32;
#pragma unroll
                for (int j = 0; j < 4; j++) pa[j] = *(const float4*)(p + j * 4);
            } else {
#pragma unroll
                for (int j = 0; j < 4; j++) pa[j] = make_float4(0.f, 0.f, 0.f, 0.f);
            }
        } else {
            if (atok >= 0) {
                const __half* p = ap16 + (size_t)it * 32;
                qa[0] = *(const uint4*)(p);
                qa[1] = *(const uint4*)(p + 8);
            } else {
                qa[0] = make_uint4(0, 0, 0, 0);
                qa[1] = make_uint4(0, 0, 0, 0);
            }
        }
        const uint32_t* pB = bp + (size_t)it * 16 * NDIM;   // 16 k-pairs per iter
        qb[0] = *(const uint4*)(pB);
        qb[1] = *(const uint4*)(pB + 4);
    };

    auto sts = [&](int b) {
        if (GELU) {
            uint4 w0, w1;
            w0.x = pack_h2(pa[0].x, pa[0].y);
            w0.y = pack_h2(pa[0].z, pa[0].w);
            w0.z = pack_h2(pa[1].x, pa[1].y);
            w0.w = pack_h2(pa[1].z, pa[1].w);
            w1.x = pack_h2(pa[2].x, pa[2].y);
            w1.y = pack_h2(pa[2].z, pa[2].w);
            w1.z = pack_h2(pa[3].x, pa[3].y);
            w1.w = pack_h2(pa[3].z, pa[3].w);
            *(uint4*)&As[b][a_sts]     = w0;
            *(uint4*)&As[b][a_sts + 4] = w1;
        } else {
            *(uint4*)&As[b][a_sts]     = qa[0];
            *(uint4*)&As[b][a_sts + 4] = qa[1];
        }
        *(uint4*)&Bs[b][b_sts]     = qb[0];
        *(uint4*)&Bs[b][b_sts + 4] = qb[1];
    };

    load(0);
    sts(0);
    __syncthreads();

    for (int it = 0; it < NIT; it++) {
        if (it + 1 < NIT) load(it + 1);
        int b = it & 1;

#pragma unroll
        for (int ks = 0; ks < 2; ks++) {
            uint32_t ah[4][4];
#pragma unroll
            for (int mb = 0; mb < 4; mb++) {
                int base = (wm + mb * 16 + gid) * AST + ks * 8 + tig;
                ah[mb][0] = As[b][base];
                ah[mb][1] = As[b][base + 8 * AST];
                ah[mb][2] = As[b][base + 4];
                ah[mb][3] = As[b][base + 8 * AST + 4];
            }
            uint32_t bh[4][2];
#pragma unroll
            for (int nb = 0; nb < 4; nb++) {
                int base = (ks * 8 + tig) * BST + wn + nb * 8 + gid;
                bh[nb][0] = Bs[b][base];
                bh[nb][1] = Bs[b][base + 4 * BST];
            }
#pragma unroll
            for (int mb = 0; mb < 4; mb++)
#pragma unroll
                for (int nb = 0; nb < 4; nb++)
                    mma16816f(acc[mb][nb], ah[mb], bh[nb][0], bh[nb][1]);
        }

        if (it + 1 < NIT) sts((it + 1) & 1);
        __syncthreads();
    }

    // ---- epilogue ----
    const float* be = bias + (size_t)e * NDIM + n0;
#pragma unroll
    for (int mb = 0; mb < 4; mb++) {
#pragma unroll
        for (int half = 0; half < 2; half++) {
            int rm = wm + mb * 16 + gid + half * 8;
            int tok = toks[rm];
            if (tok < 0) continue;
#pragma unroll
            for (int nb = 0; nb < 4; nb++) {
                int cn = wn + nb * 8 + 2 * tig;
                float v0 = acc[mb][nb][half * 2 + 0] + __ldg(be + cn);
                float v1 = acc[mb][nb][half * 2 + 1] + __ldg(be + cn + 1);
                if (GELU) {
                    v0 = v0 / (1.0f + expf(-1.702f * v0));
                    v1 = v1 / (1.0f + expf(-1.702f * v1));
                    size_t o = ((size_t)tok * NDIM + n0 + cn) >> 1;
                    ((uint32_t*)g_H)[o] = pack_h2(v0, v1);
                } else {
                    float g = gw[rm];
                    *(float2*)(out + (size_t)tok * NDIM + n0 + cn) =
                        make_float2(v0 * g, v1 * g);
                }
            }
        }
    }
}

// ---------------- launch ----------------
extern "C" void kernel_launch(void* const* d_in, const int* in_sizes, int n_in,
                              void* d_out, int out_size) {
    const float* x  = (const float*)d_in[0];
    const float* wg = (const float*)d_in[1];
    const float* bg = (const float*)d_in[2];
    const float* w1 = (const float*)d_in[3];
    const float* b1 = (const float*)d_in[4];
    const float* w2 = (const float*)d_in[5];
    const float* b2 = (const float*)d_in[6];
    float* out = (float*)d_out;

    // real device addresses of prepack outputs (NOT host shadow symbols)
    uint32_t *w1p, *w2p;
    cudaGetSymbolAddress((void**)&w1p, g_w1p);
    cudaGetSymbolAddress((void**)&w2p, g_w2p);

    init_kernel<<<1, 32>>>();
    gate_kernel<<<(NT * 32 + 255) / 256, 256>>>(x, wg, bg);
    colsum_kernel<<<NE, 256>>>();
    loss_kernel<<<1, 32>>>(out, out_size - 1);

    // pre-pack weights to fp16 k-pair layout
    {
        int n1 = NE * (D / 2) * (HD / 8);
        prepack_kernel<D, HD><<<(n1 + 255) / 256, 256>>>(w1, w1p);
        int n2 = NE * (HD / 2) * (D / 8);
        prepack_kernel<HD, D><<<(n2 + 255) / 256, 256>>>(w2, w2p);
    }

    // GEMM1: H = gelu(x @ w1 + b1) -> g_H (fp16)
    ffn_fp16<D, HD, true><<<dim3(HD / 128, NT / 128, NE), 256>>>(x, b1, nullptr);
    // GEMM2: out = (H @ w2 + b2) * gate
    ffn_fp16<HD, D, false><<<dim3(D / 128, NT / 128, NE), 256>>>(nullptr, b2, out);
}

// round 12
// speedup vs baseline: 14.6192x; 1.0156x over previous
#include <cuda_runtime.h>
#include <cuda_fp16.h>
#include <math.h>
#include <stdint.h>

// Problem constants
static constexpr int NT  = 4096;
static constexpr int D   = 1024;
static constexpr int HD  = 4096;
static constexpr int NE  = 8;
static constexpr float CAPF = 4096.0f;
static constexpr float GEPS = 1e-6f;

// ---------------- device scratch ----------------
__device__ int   g_expert[NT];
__device__ float g_score[NT];
__device__ int   g_cnt[NE];
__device__ int   g_list[NE][NT];
__device__ float g_colsum[NE];
__device__ __half g_H[(size_t)NT * HD];                     // hidden acts, fp16
__device__ uint32_t g_w1p[(size_t)NE * (D / 2) * HD];        // k-pair packed fp16
__device__ uint32_t g_w2p[(size_t)NE * (HD / 2) * D];
__device__ float g_part[(size_t)4 * NT * D];                 // GEMM2 K-split partials

// ---------------- helpers ----------------
__device__ __forceinline__ uint32_t smem_u32(const void* p) {
    uint32_t a;
    asm("{ .reg .u64 t; cvta.to.shared.u64 t, %1; cvt.u32.u64 %0, t; }" : "=r"(a) : "l"(p));
    return a;
}

__device__ __forceinline__ uint32_t pack_h2(float a, float b) {
    __half2 h = __floats2half2_rn(a, b);   // a -> low half
    return *reinterpret_cast<uint32_t*>(&h);
}

__device__ __forceinline__ void ldsm4(uint32_t* r, uint32_t a) {
    asm volatile("ldmatrix.sync.aligned.m8n8.x4.shared.b16 {%0,%1,%2,%3}, [%4];"
                 : "=r"(r[0]), "=r"(r[1]), "=r"(r[2]), "=r"(r[3]) : "r"(a));
}

__device__ __forceinline__ void mma16816f(float* c, const uint32_t* a, uint32_t b0, uint32_t b1) {
    asm volatile(
        "mma.sync.aligned.m16n8k16.row.col.f32.f16.f16.f32 "
        "{%0,%1,%2,%3}, {%4,%5,%6,%7}, {%8,%9}, {%0,%1,%2,%3};"
        : "+f"(c[0]), "+f"(c[1]), "+f"(c[2]), "+f"(c[3])
        : "r"(a[0]), "r"(a[1]), "r"(a[2]), "r"(a[3]), "r"(b0), "r"(b1));
}

// ---------------- small kernels (proven) ----------------
__global__ void init_kernel() {
    int t = threadIdx.x;
    if (t < NE) { g_cnt[t] = 0; g_colsum[t] = 0.0f; }
}

__global__ void gate_kernel(const float* __restrict__ x,
                            const float* __restrict__ wg,
                            const float* __restrict__ bg) {
    int tok  = (blockIdx.x * blockDim.x + threadIdx.x) >> 5;
    int lane = threadIdx.x & 31;
    if (tok >= NT) return;
    const float* xr = x + (size_t)tok * D;
    float acc[NE];
#pragma unroll
    for (int e = 0; e < NE; e++) acc[e] = 0.0f;
    for (int i = lane; i < D; i += 32) {
        float xv = xr[i];
        const float* wr = wg + (size_t)i * NE;
#pragma unroll
        for (int e = 0; e < NE; e++) acc[e] = fmaf(xv, wr[e], acc[e]);
    }
#pragma unroll
    for (int off = 16; off; off >>= 1)
#pragma unroll
        for (int e = 0; e < NE; e++)
            acc[e] += __shfl_xor_sync(0xffffffffu, acc[e], off);
    if (lane == 0) {
        float l[NE];
        l[0] = acc[0] + bg[0];
        float m = l[0]; int a = 0;
#pragma unroll
        for (int e = 1; e < NE; e++) {
            l[e] = acc[e] + bg[e];
            if (l[e] > m) { m = l[e]; a = e; }
        }
        float s = 0.0f;
#pragma unroll
        for (int e = 0; e < NE; e++) s += expf(l[e] - m);
        g_expert[tok] = a;
        g_score[tok]  = 1.0f / s;
        int pos = atomicAdd(&g_cnt[a], 1);
        g_list[a][pos] = tok;
    }
}

__global__ void colsum_kernel() {
    __shared__ float red[256];
    int e = blockIdx.x;
    float s = 0.0f;
    for (int n = threadIdx.x; n < NT; n += 256)
        if (g_expert[n] == e) s += g_score[n];
    red[threadIdx.x] = s;
    __syncthreads();
    for (int o = 128; o; o >>= 1) {
        if (threadIdx.x < o) red[threadIdx.x] += red[threadIdx.x + o];
        __syncthreads();
    }
    if (threadIdx.x == 0) g_colsum[e] = red[0];
}

__global__ void loss_kernel(float* __restrict__ out, int loss_idx) {
    if (threadIdx.x == 0 && blockIdx.x == 0) {
        float load[NE], tot = 0.0f;
#pragma unroll
        for (int e = 0; e < NE; e++) {
            float c = g_colsum[e];
            load[e] = c * CAPF / (c + GEPS);
            tot += load[e];
        }
        float imp = tot / (float)NT;
        float l = 0.0f;
#pragma unroll
        for (int e = 0; e < NE; e++) { float d = load[e] - imp; l += d * d; }
        out[loss_idx] = l / (float)NE;
    }
}

// ---------------- weight pre-pack (proven) ----------------
template <int K, int N>
__global__ void __launch_bounds__(256)
prepack_kernel(const float* __restrict__ W, uint32_t* __restrict__ P) {
    int idx = blockIdx.x * 256 + threadIdx.x;
    constexpr int N8 = N / 8;
    if (idx >= NE * (K / 2) * N8) return;
    int n8 = idx % N8;
    int kp = (idx / N8) % (K / 2);
    int e  = idx / (N8 * (K / 2));
    const float* r0 = W + ((size_t)e * K + 2 * kp) * N + n8 * 8;
    const float* r1 = r0 + N;
    float4 a0 = *(const float4*)(r0);
    float4 a1 = *(const float4*)(r0 + 4);
    float4 b0 = *(const float4*)(r1);
    float4 b1 = *(const float4*)(r1 + 4);
    uint4 w0, w1;
    w0.x = pack_h2(a0.x, b0.x);
    w0.y = pack_h2(a0.y, b0.y);
    w0.z = pack_h2(a0.z, b0.z);
    w0.w = pack_h2(a0.w, b0.w);
    w1.x = pack_h2(a1.x, b1.x);
    w1.y = pack_h2(a1.y, b1.y);
    w1.z = pack_h2(a1.z, b1.z);
    w1.w = pack_h2(a1.w, b1.w);
    uint32_t* dst = P + ((size_t)e * (K / 2) + kp) * N + n8 * 8;
    *(uint4*)(dst)     = w0;
    *(uint4*)(dst + 4) = w1;
}

// ---------------- fp16 tensor GEMM ----------------
// CTA 128m x 128n, BK=32, double-buffered, 8 warps (2m x 4n), 2 CTAs/SM.
// A-fragments via ldmatrix.x4 (same smem layout); B via scalar LDS (proven).
// KSTRIDE: A row stride / total weight K.  KLEN: K per CTA.  NSPLIT: K-split.
static constexpr int AST = 20;
static constexpr int BST = 136;

template <int KSTRIDE, int KLEN, int NDIM, bool GELU, int NSPLIT>
__global__ void __launch_bounds__(256, 2)
ffn_fp16(const float* __restrict__ xA,   // GEMM1: fp32 activations (null for GEMM2)
         const float* __restrict__ bias, // [NE][NDIM]
         float* __restrict__ out) {
    __shared__ uint32_t As[2][128 * AST];
    __shared__ uint32_t Bs[2][16 * BST];
    __shared__ int   toks[128];
    __shared__ float gw[128];

    int e = blockIdx.z / NSPLIT;
    int split = blockIdx.z % NSPLIT;
    int cnt = g_cnt[e];
    int mstart = blockIdx.y * 128;
    if (mstart >= cnt) return;
    int n0 = blockIdx.x * 128;

    int tid = threadIdx.x;
    int wid = tid >> 5, lane = tid & 31;

    if (tid < 128) {
        int rr = mstart + tid;
        int tok = (rr < cnt) ? g_list[e][rr] : -1;
        toks[tid] = tok;
        if (!GELU && NSPLIT == 1) {
            float g = 0.0f;
            if (tok >= 0) g = g_score[tok] * CAPF / (g_colsum[e] + GEPS);
            gw[tid] = g;
        }
    }
    __syncthreads();

    // ---- loader assignments ----
    int ar = tid >> 1;
    int ahalf = tid & 1;
    int atok = toks[ar];
    size_t arow = (size_t)(atok >= 0 ? atok : 0);
    const float*  ap32 = xA ? (xA + arow * KSTRIDE + split * KLEN + ahalf * 16) : nullptr;
    const __half* ap16 = g_H + arow * KSTRIDE + split * KLEN + ahalf * 16;
    uint32_t a_sts = (uint32_t)(ar * AST + ahalf * 8);

    int kp = tid >> 4;
    int nb8 = (tid & 15) * 8;
    const uint32_t* Wp = GELU ? g_w1p : g_w2p;
    const uint32_t* bp = Wp + ((size_t)e * (KSTRIDE / 2) + split * (KLEN / 2) + kp) * NDIM
                           + n0 + nb8;
    uint32_t b_sts = (uint32_t)(kp * BST + nb8);

    // warp tile coords
    int wm = (wid & 1) * 64;
    int wn = (wid >> 1) * 32;
    int gid = lane >> 2, tig = lane & 3;

    // ldmatrix lane-addressing for A: lane L -> row wm+(L&15)+mb*16, word (L>>4)*4
    uint32_t asb0 = smem_u32(&As[0][0]);
    uint32_t asb1 = smem_u32(&As[1][0]);
    uint32_t a_ld = (uint32_t)(((wm + (lane & 15)) * AST + (lane >> 4) * 4) * 4);

    float acc[4][4][4];
#pragma unroll
    for (int mb = 0; mb < 4; mb++)
#pragma unroll
        for (int nb = 0; nb < 4; nb++)
#pragma unroll
            for (int q = 0; q < 4; q++) acc[mb][nb][q] = 0.0f;

    constexpr int NIT = KLEN / 32;

    float4 pa[4];
    uint4  qa[2];
    uint4  qb[2];

    auto load = [&](int it) {
        if (GELU) {
            if (atok >= 0) {
                const float* p = ap32 + (size_t)it * 32;
#pragma unroll
                for (int j = 0; j < 4; j++) pa[j] = *(const float4*)(p + j * 4);
            } else {
#pragma unroll
                for (int j = 0; j < 4; j++) pa[j] = make_float4(0.f, 0.f, 0.f, 0.f);
            }
        } else {
            if (atok >= 0) {
                const __half* p = ap16 + (size_t)it * 32;
                qa[0] = *(const uint4*)(p);
                qa[1] = *(const uint4*)(p + 8);
            } else {
                qa[0] = make_uint4(0, 0, 0, 0);
                qa[1] = make_uint4(0, 0, 0, 0);
            }
        }
        const uint32_t* pB = bp + (size_t)it * 16 * NDIM;
        qb[0] = *(const uint4*)(pB);
        qb[1] = *(const uint4*)(pB + 4);
    };

    auto sts = [&](int b) {
        if (GELU) {
            uint4 w0, w1;
            w0.x = pack_h2(pa[0].x, pa[0].y);
            w0.y = pack_h2(pa[0].z, pa[0].w);
            w0.z = pack_h2(pa[1].x, pa[1].y);
            w0.w = pack_h2(pa[1].z, pa[1].w);
            w1.x = pack_h2(pa[2].x, pa[2].y);
            w1.y = pack_h2(pa[2].z, pa[2].w);
            w1.z = pack_h2(pa[3].x, pa[3].y);
            w1.w = pack_h2(pa[3].z, pa[3].w);
            *(uint4*)&As[b][a_sts]     = w0;
            *(uint4*)&As[b][a_sts + 4] = w1;
        } else {
            *(uint4*)&As[b][a_sts]     = qa[0];
            *(uint4*)&As[b][a_sts + 4] = qa[1];
        }
        *(uint4*)&Bs[b][b_sts]     = qb[0];
        *(uint4*)&Bs[b][b_sts + 4] = qb[1];
    };

    load(0);
    sts(0);
    __syncthreads();

    for (int it = 0; it < NIT; it++) {
        if (it + 1 < NIT) load(it + 1);
        int b = it & 1;
        uint32_t asb = b ? asb1 : asb0;

#pragma unroll
        for (int ks = 0; ks < 2; ks++) {
            uint32_t ah[4][4];
#pragma unroll
            for (int mb = 0; mb < 4; mb++)
                ldsm4(ah[mb], asb + a_ld + (uint32_t)((mb * 16 * AST + ks * 8) * 4));
            uint32_t bh[4][2];
#pragma unroll
            for (int nb = 0; nb < 4; nb++) {
                int base = (ks * 8 + tig) * BST + wn + nb * 8 + gid;
                bh[nb][0] = Bs[b][base];
                bh[nb][1] = Bs[b][base + 4 * BST];
            }
#pragma unroll
            for (int mb = 0; mb < 4; mb++)
#pragma unroll
                for (int nb = 0; nb < 4; nb++)
                    mma16816f(acc[mb][nb], ah[mb], bh[nb][0], bh[nb][1]);
        }

        if (it + 1 < NIT) sts((it + 1) & 1);
        __syncthreads();
    }

    // ---- epilogue ----
    const float* be = bias + (size_t)e * NDIM + n0;
#pragma unroll
    for (int mb = 0; mb < 4; mb++) {
#pragma unroll
        for (int half = 0; half < 2; half++) {
            int rm = wm + mb * 16 + gid + half * 8;
            int tok = toks[rm];
            if (tok < 0) continue;
#pragma unroll
            for (int nb = 0; nb < 4; nb++) {
                int cn = wn + nb * 8 + 2 * tig;
                float a0 = acc[mb][nb][half * 2 + 0];
                float a1 = acc[mb][nb][half * 2 + 1];
                if (GELU) {
                    float v0 = a0 + __ldg(be + cn);
                    float v1 = a1 + __ldg(be + cn + 1);
                    v0 = v0 / (1.0f + expf(-1.702f * v0));
                    v1 = v1 / (1.0f + expf(-1.702f * v1));
                    size_t o = ((size_t)tok * NDIM + n0 + cn) >> 1;
                    ((uint32_t*)g_H)[o] = pack_h2(v0, v1);
                } else if (NSPLIT > 1) {
                    // raw partial (bias+gate applied in reduce)
                    *(float2*)(g_part + ((size_t)split * NT + tok) * NDIM + n0 + cn) =
                        make_float2(a0, a1);
                } else {
                    float g = gw[rm];
                    float v0 = a0 + __ldg(be + cn);
                    float v1 = a1 + __ldg(be + cn + 1);
                    *(float2*)(out + (size_t)tok * NDIM + n0 + cn) =
                        make_float2(v0 * g, v1 * g);
                }
            }
        }
    }
}

// ---------------- deterministic K-split reduce + bias + gate ----------------
__global__ void __launch_bounds__(256)
reduce_kernel(const float* __restrict__ b2, float* __restrict__ out) {
    int tok = blockIdx.x;
    int c = threadIdx.x * 4;
    int e = g_expert[tok];
    float g = g_score[tok] * CAPF / (g_colsum[e] + GEPS);
    size_t off = (size_t)tok * D + c;
    float4 s0 = *(const float4*)(g_part + 0 * (size_t)NT * D + off);
    float4 s1 = *(const float4*)(g_part + 1 * (size_t)NT * D + off);
    float4 s2 = *(const float4*)(g_part + 2 * (size_t)NT * D + off);
    float4 s3 = *(const float4*)(g_part + 3 * (size_t)NT * D + off);
    float4 bb = *(const float4*)(b2 + (size_t)e * D + c);
    float4 r;
    r.x = (((s0.x + s1.x) + s2.x) + s3.x + bb.x) * g;
    r.y = (((s0.y + s1.y) + s2.y) + s3.y + bb.y) * g;
    r.z = (((s0.z + s1.z) + s2.z) + s3.z + bb.z) * g;
    r.w = (((s0.w + s1.w) + s2.w) + s3.w + bb.w) * g;
    *(float4*)(out + off) = r;
}

// ---------------- launch ----------------
extern "C" void kernel_launch(void* const* d_in, const int* in_sizes, int n_in,
                              void* d_out, int out_size) {
    const float* x  = (const float*)d_in[0];
    const float* wg = (const float*)d_in[1];
    const float* bg = (const float*)d_in[2];
    const float* w1 = (const float*)d_in[3];
    const float* b1 = (const float*)d_in[4];
    const float* w2 = (const float*)d_in[5];
    const float* b2 = (const float*)d_in[6];
    float* out = (float*)d_out;

    uint32_t *w1p, *w2p;
    cudaGetSymbolAddress((void**)&w1p, g_w1p);
    cudaGetSymbolAddress((void**)&w2p, g_w2p);

    init_kernel<<<1, 32>>>();
    gate_kernel<<<(NT * 32 + 255) / 256, 256>>>(x, wg, bg);
    colsum_kernel<<<NE, 256>>>();
    loss_kernel<<<1, 32>>>(out, out_size - 1);

    {
        int n1 = NE * (D / 2) * (HD / 8);
        prepack_kernel<D, HD><<<(n1 + 255) / 256, 256>>>(w1, w1p);
        int n2 = NE * (HD / 2) * (D / 8);
        prepack_kernel<HD, D><<<(n2 + 255) / 256, 256>>>(w2, w2p);
    }

    // GEMM1: H = gelu(x @ w1 + b1) -> g_H (fp16)
    ffn_fp16<D, D, HD, true, 1>
        <<<dim3(HD / 128, NT / 128, NE), 256>>>(x, b1, nullptr);
    // GEMM2 (K-split x4): partials to g_part
    ffn_fp16<HD, HD / 4, D, false, 4>
        <<<dim3(D / 128, NT / 128, NE * 4), 256>>>(nullptr, b2, nullptr);
    // reduce: out = (sum parts + b2) * gate
    reduce_kernel<<<NT, 256>>>(b2, out);
}

// round 13
// speedup vs baseline: 16.3867x; 1.1209x over previous
#include <cuda_runtime.h>
#include <cuda_fp16.h>
#include <math.h>
#include <stdint.h>

// Problem constants
static constexpr int NT  = 4096;
static constexpr int D   = 1024;
static constexpr int HD  = 4096;
static constexpr int NE  = 8;
static constexpr float CAPF = 4096.0f;
static constexpr float GEPS = 1e-6f;

// ---------------- device scratch ----------------
__device__ int   g_expert[NT];
__device__ float g_score[NT];
__device__ int   g_cnt[NE];
__device__ int   g_list[NE][NT];
__device__ float g_colsum[NE];
__device__ __half g_Xh[(size_t)NT * D];                      // x in fp16
__device__ __half g_H[(size_t)NT * HD];                      // hidden acts, fp16
__device__ uint32_t g_w1p[(size_t)NE * (D / 2) * HD];        // k-pair packed fp16
__device__ uint32_t g_w2p[(size_t)NE * (HD / 2) * D];
__device__ float g_part[(size_t)4 * NT * D];                 // GEMM2 K-split partials

// ---------------- helpers ----------------
__device__ __forceinline__ uint32_t smem_u32(const void* p) {
    uint32_t a;
    asm("{ .reg .u64 t; cvta.to.shared.u64 t, %1; cvt.u32.u64 %0, t; }" : "=r"(a) : "l"(p));
    return a;
}

__device__ __forceinline__ uint32_t pack_h2(float a, float b) {
    __half2 h = __floats2half2_rn(a, b);   // a -> low half
    return *reinterpret_cast<uint32_t*>(&h);
}

__device__ __forceinline__ void cpa16(uint32_t dst, const void* src, uint32_t srcsz) {
    asm volatile("cp.async.cg.shared.global [%0], [%1], 16, %2;"
                 :: "r"(dst), "l"(src), "r"(srcsz) : "memory");
}
__device__ __forceinline__ void cpa_commit() {
    asm volatile("cp.async.commit_group;" ::: "memory");
}
__device__ __forceinline__ void cpa_wait1() {
    asm volatile("cp.async.wait_group 1;" ::: "memory");
}

__device__ __forceinline__ void ldsm4(uint32_t* r, uint32_t a) {
    asm volatile("ldmatrix.sync.aligned.m8n8.x4.shared.b16 {%0,%1,%2,%3}, [%4];"
                 : "=r"(r[0]), "=r"(r[1]), "=r"(r[2]), "=r"(r[3]) : "r"(a));
}

__device__ __forceinline__ void mma16816f(float* c, const uint32_t* a, uint32_t b0, uint32_t b1) {
    asm volatile(
        "mma.sync.aligned.m16n8k16.row.col.f32.f16.f16.f32 "
        "{%0,%1,%2,%3}, {%4,%5,%6,%7}, {%8,%9}, {%0,%1,%2,%3};"
        : "+f"(c[0]), "+f"(c[1]), "+f"(c[2]), "+f"(c[3])
        : "r"(a[0]), "r"(a[1]), "r"(a[2]), "r"(a[3]), "r"(b0), "r"(b1));
}

// ---------------- small kernels (proven) ----------------
__global__ void init_kernel() {
    int t = threadIdx.x;
    if (t < NE) { g_cnt[t] = 0; g_colsum[t] = 0.0f; }
}

__global__ void gate_kernel(const float* __restrict__ x,
                            const float* __restrict__ wg,
                            const float* __restrict__ bg) {
    int tok  = (blockIdx.x * blockDim.x + threadIdx.x) >> 5;
    int lane = threadIdx.x & 31;
    if (tok >= NT) return;
    const float* xr = x + (size_t)tok * D;
    float acc[NE];
#pragma unroll
    for (int e = 0; e < NE; e++) acc[e] = 0.0f;
    for (int i = lane; i < D; i += 32) {
        float xv = xr[i];
        const float* wr = wg + (size_t)i * NE;
#pragma unroll
        for (int e = 0; e < NE; e++) acc[e] = fmaf(xv, wr[e], acc[e]);
    }
#pragma unroll
    for (int off = 16; off; off >>= 1)
#pragma unroll
        for (int e = 0; e < NE; e++)
            acc[e] += __shfl_xor_sync(0xffffffffu, acc[e], off);
    if (lane == 0) {
        float l[NE];
        l[0] = acc[0] + bg[0];
        float m = l[0]; int a = 0;
#pragma unroll
        for (int e = 1; e < NE; e++) {
            l[e] = acc[e] + bg[e];
            if (l[e] > m) { m = l[e]; a = e; }
        }
        float s = 0.0f;
#pragma unroll
        for (int e = 0; e < NE; e++) s += expf(l[e] - m);
        g_expert[tok] = a;
        g_score[tok]  = 1.0f / s;
        int pos = atomicAdd(&g_cnt[a], 1);
        g_list[a][pos] = tok;
    }
}

__global__ void colsum_kernel() {
    __shared__ float red[256];
    int e = blockIdx.x;
    float s = 0.0f;
    for (int n = threadIdx.x; n < NT; n += 256)
        if (g_expert[n] == e) s += g_score[n];
    red[threadIdx.x] = s;
    __syncthreads();
    for (int o = 128; o; o >>= 1) {
        if (threadIdx.x < o) red[threadIdx.x] += red[threadIdx.x + o];
        __syncthreads();
    }
    if (threadIdx.x == 0) g_colsum[e] = red[0];
}

__global__ void loss_kernel(float* __restrict__ out, int loss_idx) {
    if (threadIdx.x == 0 && blockIdx.x == 0) {
        float load[NE], tot = 0.0f;
#pragma unroll
        for (int e = 0; e < NE; e++) {
            float c = g_colsum[e];
            load[e] = c * CAPF / (c + GEPS);
            tot += load[e];
        }
        float imp = tot / (float)NT;
        float l = 0.0f;
#pragma unroll
        for (int e = 0; e < NE; e++) { float d = load[e] - imp; l += d * d; }
        out[loss_idx] = l / (float)NE;
    }
}

// x fp32 -> fp16 (layout preserved), 8 values/thread
__global__ void __launch_bounds__(256)
xsplit_kernel(const float* __restrict__ x, int n8) {
    int i = blockIdx.x * 256 + threadIdx.x;
    if (i >= n8) return;
    const float4* s = (const float4*)x + (size_t)i * 2;
    float4 v0 = s[0], v1 = s[1];
    uint4 w;
    w.x = pack_h2(v0.x, v0.y);
    w.y = pack_h2(v0.z, v0.w);
    w.z = pack_h2(v1.x, v1.y);
    w.w = pack_h2(v1.z, v1.w);
    ((uint4*)g_Xh)[i] = w;
}

// ---------------- weight pre-pack (proven) ----------------
template <int K, int N>
__global__ void __launch_bounds__(256)
prepack_kernel(const float* __restrict__ W, uint32_t* __restrict__ P) {
    int idx = blockIdx.x * 256 + threadIdx.x;
    constexpr int N8 = N / 8;
    if (idx >= NE * (K / 2) * N8) return;
    int n8 = idx % N8;
    int kp = (idx / N8) % (K / 2);
    int e  = idx / (N8 * (K / 2));
    const float* r0 = W + ((size_t)e * K + 2 * kp) * N + n8 * 8;
    const float* r1 = r0 + N;
    float4 a0 = *(const float4*)(r0);
    float4 a1 = *(const float4*)(r0 + 4);
    float4 b0 = *(const float4*)(r1);
    float4 b1 = *(const float4*)(r1 + 4);
    uint4 w0, w1;
    w0.x = pack_h2(a0.x, b0.x);
    w0.y = pack_h2(a0.y, b0.y);
    w0.z = pack_h2(a0.z, b0.z);
    w0.w = pack_h2(a0.w, b0.w);
    w1.x = pack_h2(a1.x, b1.x);
    w1.y = pack_h2(a1.y, b1.y);
    w1.z = pack_h2(a1.z, b1.z);
    w1.w = pack_h2(a1.w, b1.w);
    uint32_t* dst = P + ((size_t)e * (K / 2) + kp) * N + n8 * 8;
    *(uint4*)(dst)     = w0;
    *(uint4*)(dst + 4) = w1;
}

// ---------------- fp16 tensor GEMM, cp.async 3-stage ----------------
// CTA 128m x 128n, BK=32, 8 warps (2m x 4n), 2 CTAs/SM.
// A via ldmatrix.x4 (layout proven in R12); B via scalar LDS (proven).
static constexpr int AST = 20;                   // A row stride, words
static constexpr int BST = 136;                  // B row stride, words
static constexpr int AS_W = 128 * AST;           // 2560 words / stage
static constexpr int BS_W = 16 * BST;            // 2176 words / stage
static constexpr int SMEM_BYTES = 3 * (AS_W + BS_W) * 4;   // 56832

template <int KSTRIDE, int KLEN, int NDIM, bool GELU, int NSPLIT>
__global__ void __launch_bounds__(256, 2)
ffn_fp16(const float* __restrict__ bias,  // [NE][NDIM]
         float* __restrict__ out) {
    extern __shared__ uint32_t dyn[];
    uint32_t* AsBase = dyn;               // [3][AS_W]
    uint32_t* BsBase = dyn + 3 * AS_W;    // [3][BS_W]
    __shared__ int   toks[128];
    __shared__ float gw[128];

    int e = blockIdx.z / NSPLIT;
    int split = blockIdx.z % NSPLIT;
    int cnt = g_cnt[e];
    int mstart = blockIdx.y * 128;
    if (mstart >= cnt) return;
    int n0 = blockIdx.x * 128;

    int tid = threadIdx.x;
    int wid = tid >> 5, lane = tid & 31;

    if (tid < 128) {
        int rr = mstart + tid;
        int tok = (rr < cnt) ? g_list[e][rr] : -1;
        toks[tid] = tok;
        if (!GELU && NSPLIT == 1) {
            float g = 0.0f;
            if (tok >= 0) g = g_score[tok] * CAPF / (g_colsum[e] + GEPS);
            gw[tid] = g;
        }
    }
    __syncthreads();

    uint32_t asb = smem_u32(AsBase);
    uint32_t bsb = smem_u32(BsBase);

    // ---- cp.async assignments ----
    // A: thread t -> row r=t>>1, 32B half h=t&1; 2x16B per iter
    int ar = tid >> 1;
    int atok = toks[ar];
    size_t arow = (size_t)(atok >= 0 ? atok : 0);
    const __half* aGlob = GELU ? g_Xh : g_H;
    const char* aSrc = (const char*)(aGlob + arow * KSTRIDE + split * KLEN) + (tid & 1) * 32;
    uint32_t a_dst = (uint32_t)(ar * 80 + (tid & 1) * 32);
    uint32_t asz = (atok >= 0) ? 16u : 0u;

    // B: thread t -> kpair kp=t>>4, 32B chunk (t&15); 2x16B per iter
    const uint32_t* Wp = GELU ? g_w1p : g_w2p;
    const char* bSrc = (const char*)(Wp + ((size_t)e * (KSTRIDE / 2) + split * (KLEN / 2)
                                           + (tid >> 4)) * NDIM + n0 + (tid & 15) * 8);
    uint32_t b_dst = (uint32_t)((tid >> 4) * 544 + (tid & 15) * 32);

    auto issue = [&](int it) {
        uint32_t s = (uint32_t)(it % 3);
        uint32_t ad = asb + s * (AS_W * 4) + a_dst;
        const char* ap = aSrc + (size_t)it * 64;          // 32 halfs per iter
        cpa16(ad, ap, asz);
        cpa16(ad + 16, ap + 16, asz);
        uint32_t bd = bsb + s * (BS_W * 4) + b_dst;
        const char* bq = bSrc + (size_t)it * 16 * NDIM * 4; // 16 kpair rows per iter
        cpa16(bd, bq, 16u);
        cpa16(bd + 16, bq + 16, 16u);
        cpa_commit();
    };

    // warp tile coords
    int wm = (wid & 1) * 64;
    int wn = (wid >> 1) * 32;
    int gid = lane >> 2, tig = lane & 3;
    uint32_t a_ld = (uint32_t)(((wm + (lane & 15)) * AST + (lane >> 4) * 4) * 4);

    float acc[4][4][4];
#pragma unroll
    for (int mb = 0; mb < 4; mb++)
#pragma unroll
        for (int nb = 0; nb < 4; nb++)
#pragma unroll
            for (int q = 0; q < 4; q++) acc[mb][nb][q] = 0.0f;

    constexpr int NIT = KLEN / 32;

    issue(0);
    issue(1);

    for (int it = 0; it < NIT; it++) {
        cpa_wait1();          // stage it%3 landed (groups 0..it complete)
        __syncthreads();
        if (it + 2 < NIT) issue(it + 2);
        else cpa_commit();    // keep group numbering aligned

        uint32_t sA = asb + (uint32_t)(it % 3) * (AS_W * 4);
        const uint32_t* BsS = BsBase + (it % 3) * BS_W;

#pragma unroll
        for (int ks = 0; ks < 2; ks++) {
            uint32_t ah[4][4];
#pragma unroll
            for (int mb = 0; mb < 4; mb++)
                ldsm4(ah[mb], sA + a_ld + (uint32_t)((mb * 16 * AST + ks * 8) * 4));
            uint32_t bh[4][2];
#pragma unroll
            for (int nb = 0; nb < 4; nb++) {
                int base = (ks * 8 + tig) * BST + wn + nb * 8 + gid;
                bh[nb][0] = BsS[base];
                bh[nb][1] = BsS[base + 4 * BST];
            }
#pragma unroll
            for (int mb = 0; mb < 4; mb++)
#pragma unroll
                for (int nb = 0; nb < 4; nb++)
                    mma16816f(acc[mb][nb], ah[mb], bh[nb][0], bh[nb][1]);
        }
    }

    // ---- epilogue ----
    const float* be = bias + (size_t)e * NDIM + n0;
#pragma unroll
    for (int mb = 0; mb < 4; mb++) {
#pragma unroll
        for (int half = 0; half < 2; half++) {
            int rm = wm + mb * 16 + gid + half * 8;
            int tok = toks[rm];
            if (tok < 0) continue;
#pragma unroll
            for (int nb = 0; nb < 4; nb++) {
                int cn = wn + nb * 8 + 2 * tig;
                float a0 = acc[mb][nb][half * 2 + 0];
                float a1 = acc[mb][nb][half * 2 + 1];
                if (GELU) {
                    float v0 = a0 + __ldg(be + cn);
                    float v1 = a1 + __ldg(be + cn + 1);
                    v0 = v0 / (1.0f + expf(-1.702f * v0));
                    v1 = v1 / (1.0f + expf(-1.702f * v1));
                    size_t o = ((size_t)tok * NDIM + n0 + cn) >> 1;
                    ((uint32_t*)g_H)[o] = pack_h2(v0, v1);
                } else if (NSPLIT > 1) {
                    *(float2*)(g_part + ((size_t)split * NT + tok) * NDIM + n0 + cn) =
                        make_float2(a0, a1);
                } else {
                    float g = gw[rm];
                    float v0 = a0 + __ldg(be + cn);
                    float v1 = a1 + __ldg(be + cn + 1);
                    *(float2*)(out + (size_t)tok * NDIM + n0 + cn) =
                        make_float2(v0 * g, v1 * g);
                }
            }
        }
    }
}

// ---------------- deterministic K-split reduce + bias + gate ----------------
__global__ void __launch_bounds__(256)
reduce_kernel(const float* __restrict__ b2, float* __restrict__ out) {
    int tok = blockIdx.x;
    int c = threadIdx.x * 4;
    int e = g_expert[tok];
    float g = g_score[tok] * CAPF / (g_colsum[e] + GEPS);
    size_t off = (size_t)tok * D + c;
    float4 s0 = *(const float4*)(g_part + 0 * (size_t)NT * D + off);
    float4 s1 = *(const float4*)(g_part + 1 * (size_t)NT * D + off);
    float4 s2 = *(const float4*)(g_part + 2 * (size_t)NT * D + off);
    float4 s3 = *(const float4*)(g_part + 3 * (size_t)NT * D + off);
    float4 bb = *(const float4*)(b2 + (size_t)e * D + c);
    float4 r;
    r.x = (((s0.x + s1.x) + s2.x) + s3.x + bb.x) * g;
    r.y = (((s0.y + s1.y) + s2.y) + s3.y + bb.y) * g;
    r.z = (((s0.z + s1.z) + s2.z) + s3.z + bb.z) * g;
    r.w = (((s0.w + s1.w) + s2.w) + s3.w + bb.w) * g;
    *(float4*)(out + off) = r;
}

// ---------------- launch ----------------
extern "C" void kernel_launch(void* const* d_in, const int* in_sizes, int n_in,
                              void* d_out, int out_size) {
    const float* x  = (const float*)d_in[0];
    const float* wg = (const float*)d_in[1];
    const float* bg = (const float*)d_in[2];
    const float* w1 = (const float*)d_in[3];
    const float* b1 = (const float*)d_in[4];
    const float* w2 = (const float*)d_in[5];
    const float* b2 = (const float*)d_in[6];
    float* out = (float*)d_out;

    uint32_t *w1p, *w2p;
    cudaGetSymbolAddress((void**)&w1p, g_w1p);
    cudaGetSymbolAddress((void**)&w2p, g_w2p);

    cudaFuncSetAttribute(ffn_fp16<D, D, HD, true, 1>,
                         cudaFuncAttributeMaxDynamicSharedMemorySize, SMEM_BYTES);
    cudaFuncSetAttribute(ffn_fp16<HD, HD / 4, D, false, 4>,
                         cudaFuncAttributeMaxDynamicSharedMemorySize, SMEM_BYTES);

    init_kernel<<<1, 32>>>();
    gate_kernel<<<(NT * 32 + 255) / 256, 256>>>(x, wg, bg);
    colsum_kernel<<<NE, 256>>>();
    loss_kernel<<<1, 32>>>(out, out_size - 1);

    xsplit_kernel<<<(NT * D / 8 + 255) / 256, 256>>>(x, NT * D / 8);
    {
        int n1 = NE * (D / 2) * (HD / 8);
        prepack_kernel<D, HD><<<(n1 + 255) / 256, 256>>>(w1, w1p);
        int n2 = NE * (HD / 2) * (D / 8);
        prepack_kernel<HD, D><<<(n2 + 255) / 256, 256>>>(w2, w2p);
    }

    // GEMM1: H = gelu(x @ w1 + b1) -> g_H (fp16)
    ffn_fp16<D, D, HD, true, 1>
        <<<dim3(HD / 128, NT / 128, NE), 256, SMEM_BYTES>>>(b1, nullptr);
    // GEMM2 (K-split x4): partials to g_part
    ffn_fp16<HD, HD / 4, D, false, 4>
        <<<dim3(D / 128, NT / 128, NE * 4), 256, SMEM_BYTES>>>(b2, nullptr);
    // reduce: out = (sum parts + b2) * gate
    reduce_kernel<<<NT, 256>>>(b2, out);
}